// round 2
// baseline (speedup 1.0000x reference)
#include <cuda_runtime.h>
#include <math.h>
#include <stdint.h>

#define Nn    20000
#define Ee    320000
#define FIN   128
#define H1c   64
#define H2c   128
#define HEADSc 8
#define NCc   40
#define K1c   16000
#define K2c   12800

#define CDIV(a,b) (((a)+(b)-1)/(b))

// ---------------------------------------------------------------------------
// Device scratch (static, no runtime allocation)
// ---------------------------------------------------------------------------
__device__ float d_aggr[Nn*FIN];
__device__ int   d_cnt[Nn];
__device__ float d_gP[Nn*H2c];
__device__ float d_gQ[Nn*H2c];
__device__ float d_gR[Nn*H2c];
__device__ float d_h1[Nn*H1c];
__device__ float d_hp1[K1c*H1c];
__device__ float d_h2[K1c*H2c];
__device__ float d_hp2[K2c*H2c];
__device__ float d_xh[K2c*HEADSc*H2c];     // 12800 x 1024
__device__ float d_al[K2c*HEADSc];
__device__ float d_ad[K2c*HEADSc];
__device__ float d_mx[K2c*HEADSc];
__device__ float d_dn[K2c*HEADSc];
__device__ float d_gat[K2c*H2c];
__device__ float d_gin[K2c*H2c];
__device__ float d_y1[K2c*H1c];
__device__ float d_o1[K2c*H1c];
__device__ float d_y2[K2c*NCc];
__device__ float d_o2[K2c*NCc];
__device__ int   d_deg[K2c];
__device__ float d_dinv[K2c];
__device__ float d_score[Nn];
__device__ int   d_keep[Nn];
__device__ int   d_nid[Nn];
__device__ int   d_src1[Ee], d_dst1[Ee], d_src2[Ee], d_dst2[Ee];
__device__ int   d_eflag[Ee], d_escan[Ee];
__device__ int   d_ebs[1024];
__device__ int   d_Ecnt[2];
__device__ unsigned d_hist[256];
__device__ unsigned d_prefix;
__device__ int   d_krem;
__device__ float d_wni;
__device__ float d_gvec[NCc];

// ---------------------------------------------------------------------------
// Small utility kernels
// ---------------------------------------------------------------------------
__global__ void k_zero_f(float* p, int n){
    int i = blockIdx.x*blockDim.x + threadIdx.x;
    if (i < n) p[i] = 0.f;
}
__global__ void k_zero_i(int* p, int n){
    int i = blockIdx.x*blockDim.x + threadIdx.x;
    if (i < n) p[i] = 0;
}

// ---------------------------------------------------------------------------
// SAGE: scatter mean aggregation (warp per edge)
// ---------------------------------------------------------------------------
__global__ void k_scatter(const int* __restrict__ src, const int* __restrict__ dst,
                          const float* __restrict__ x, float* __restrict__ s,
                          int* __restrict__ cnt, int F, const int* pE, int Emax){
    int t = blockIdx.x*blockDim.x + threadIdx.x;
    int w = t >> 5, lane = t & 31;
    if (w >= Emax) return;
    int E = pE ? *pE : Emax;
    if (w >= E) return;
    int sn = src[w], dn = dst[w];
    const float* xr = x + (size_t)sn * F;
    float* sr = s + (size_t)dn * F;
    for (int c = lane; c < F; c += 32) atomicAdd(&sr[c], xr[c]);
    if (lane == 0) atomicAdd(&cnt[dn], 1);
}

__global__ void k_meandiv(float* s, const int* cnt, int n, int F){
    int i = blockIdx.x*blockDim.x + threadIdx.x;
    if (i >= n*F) return;
    int node = i / F;
    float c = (float)cnt[node];
    s[i] = s[i] / fmaxf(c, 1.f);
}

__global__ void k_sage_combine(const float* P, const float* Q, const float* R,
                               const float* bl, const float* rb, float* h, int n, int C){
    int i = blockIdx.x*blockDim.x + threadIdx.x;
    if (i >= n*C) return;
    int c = i % C;
    float v = P[i] + Q[i] + bl[c];
    h[i] = fmaxf(v, 0.f) + R[i] + rb[c];
}

// ---------------------------------------------------------------------------
// Tiled SGEMM: C[M,N] = A[M,K] @ B[K,N]  (row-major)
// ---------------------------------------------------------------------------
#define BM 64
#define BN 64
#define BK 16
#define TM 4
#define TN 4
__global__ void k_gemm(const float* __restrict__ A, const float* __restrict__ B,
                       float* __restrict__ C, int M, int N, int K){
    __shared__ float As[BK][BM];
    __shared__ float Bs[BK][BN];
    int tid = threadIdx.x;                // 256 threads
    int tr = tid / (BN/TN);               // 0..15
    int tc = tid % (BN/TN);               // 0..15
    int rowBase = blockIdx.y * BM;
    int colBase = blockIdx.x * BN;
    float acc[TM][TN];
    #pragma unroll
    for (int i = 0; i < TM; i++)
        #pragma unroll
        for (int j = 0; j < TN; j++) acc[i][j] = 0.f;

    for (int k0 = 0; k0 < K; k0 += BK) {
        #pragma unroll
        for (int i = tid; i < BM*BK; i += 256) {
            int r = i % BM; int kk = i / BM;
            int gr = rowBase + r, gk = k0 + kk;
            As[kk][r] = (gr < M && gk < K) ? A[gr*K + gk] : 0.f;
        }
        #pragma unroll
        for (int i = tid; i < BK*BN; i += 256) {
            int c = i % BN; int kk = i / BN;
            int gc = colBase + c, gk = k0 + kk;
            Bs[kk][c] = (gc < N && gk < K) ? B[gk*N + gc] : 0.f;
        }
        __syncthreads();
        #pragma unroll
        for (int kk = 0; kk < BK; kk++) {
            float a[TM], b[TN];
            #pragma unroll
            for (int i = 0; i < TM; i++) a[i] = As[kk][tr*TM + i];
            #pragma unroll
            for (int j = 0; j < TN; j++) b[j] = Bs[kk][tc*TN + j];
            #pragma unroll
            for (int i = 0; i < TM; i++)
                #pragma unroll
                for (int j = 0; j < TN; j++) acc[i][j] += a[i]*b[j];
        }
        __syncthreads();
    }
    #pragma unroll
    for (int i = 0; i < TM; i++) {
        int r = rowBase + tr*TM + i;
        if (r >= M) continue;
        #pragma unroll
        for (int j = 0; j < TN; j++) {
            int c = colBase + tc*TN + j;
            if (c < N) C[r*N + c] = acc[i][j];
        }
    }
}

// ---------------------------------------------------------------------------
// TopK pooling: score + exact radix select of K-th largest + stable tie-break
// ---------------------------------------------------------------------------
__global__ void k_wnorm(const float* w, int n){
    __shared__ float sh[128];
    float s = 0;
    for (int i = threadIdx.x; i < n; i += 128) { float v = w[i]; s += v*v; }
    sh[threadIdx.x] = s; __syncthreads();
    for (int o = 64; o; o >>= 1) {
        if (threadIdx.x < o) sh[threadIdx.x] += sh[threadIdx.x + o];
        __syncthreads();
    }
    if (threadIdx.x == 0) d_wni = rsqrtf(sh[0]);
}

__global__ void k_score(const float* __restrict__ h, const float* __restrict__ w,
                        float* score, int n, int F){
    int i = blockIdx.x*blockDim.x + threadIdx.x;
    if (i >= n) return;
    const float* r = h + (size_t)i * F;
    float s = 0;
    for (int c = 0; c < F; c++) s += r[c]*w[c];
    score[i] = tanhf(s * d_wni);
}

__device__ __forceinline__ unsigned fkey(float f){
    unsigned u = __float_as_uint(f);
    return (u & 0x80000000u) ? ~u : (u | 0x80000000u);
}

__global__ void k_rs_init(int K){
    if (threadIdx.x == 0) { d_prefix = 0u; d_krem = K; }
}
__global__ void k_rs_clear(){ d_hist[threadIdx.x] = 0u; }
__global__ void k_rs_hist(const float* score, int n, int pass){
    int i = blockIdx.x*blockDim.x + threadIdx.x;
    if (i >= n) return;
    unsigned key = fkey(score[i]);
    int shift = 24 - 8*pass;
    if (pass > 0) {
        unsigned hm = 0xFFFFFFFFu << (shift + 8);
        if ((key & hm) != (d_prefix & hm)) return;
    }
    atomicAdd(&d_hist[(key >> shift) & 0xFFu], 1u);
}
__global__ void k_rs_select(int pass){
    if (threadIdx.x || blockIdx.x) return;
    int shift = 24 - 8*pass;
    unsigned k = (unsigned)d_krem, cum = 0; int b = 0;
    for (int i = 255; i >= 0; i--) {
        unsigned c = d_hist[i];
        if (cum + c >= k) { b = i; break; }
        cum += c;
    }
    d_prefix |= ((unsigned)b) << shift;
    d_krem = (int)(k - cum);
}
__global__ void k_tie_flag(const float* score, int* tf, int n){
    int i = blockIdx.x*blockDim.x + threadIdx.x;
    if (i >= n) return;
    tf[i] = (fkey(score[i]) == d_prefix) ? 1 : 0;
}
// stable: among ties, keep the d_krem lowest indices (matches XLA top_k)
__global__ void k_keep(const float* score, const int* tf, const int* trank,
                       int* keep, int n){
    int i = blockIdx.x*blockDim.x + threadIdx.x;
    if (i >= n) return;
    unsigned key = fkey(score[i]);
    int kp = (key > d_prefix) ? 1 : 0;
    if (!kp && tf[i] && trank[i] < d_krem) kp = 1;
    keep[i] = kp;
}

// ---------------------------------------------------------------------------
// Exclusive scan (3-kernel: 512/block, <=1024 blocks)
// ---------------------------------------------------------------------------
__global__ void k_scan1(const int* in, int* out, int* bs, int n){
    __shared__ int sh[512];
    int g = blockIdx.x*512 + threadIdx.x;
    int v = (g < n) ? in[g] : 0;
    sh[threadIdx.x] = v; __syncthreads();
    for (int o = 1; o < 512; o <<= 1) {
        int t = (threadIdx.x >= o) ? sh[threadIdx.x - o] : 0;
        __syncthreads();
        sh[threadIdx.x] += t;
        __syncthreads();
    }
    if (g < n) out[g] = sh[threadIdx.x] - v;
    if (threadIdx.x == 511) bs[blockIdx.x] = sh[511];
}
__global__ void k_scan2(int* bs, int nb, int* total){
    __shared__ int sh[1024];
    int v = (threadIdx.x < nb) ? bs[threadIdx.x] : 0;
    sh[threadIdx.x] = v; __syncthreads();
    for (int o = 1; o < 1024; o <<= 1) {
        int t = (threadIdx.x >= o) ? sh[threadIdx.x - o] : 0;
        __syncthreads();
        sh[threadIdx.x] += t;
        __syncthreads();
    }
    if (threadIdx.x < nb) bs[threadIdx.x] = sh[threadIdx.x] - v;
    if (threadIdx.x == 1023 && total) *total = sh[1023];
}
__global__ void k_scan3(int* out, const int* bs, int n){
    int g = blockIdx.x*512 + threadIdx.x;
    if (g < n) out[g] += bs[blockIdx.x];
}

// ---------------------------------------------------------------------------
// Pool gather + edge compaction
// ---------------------------------------------------------------------------
__global__ void k_pool_gather(const float* h, const float* score, const int* keep,
                              const int* nid, float* out, int n, int F){
    int i = blockIdx.x*blockDim.x + threadIdx.x;
    if (i >= n*F) return;
    int node = i / F, c = i % F;
    if (keep[node]) out[(size_t)nid[node]*F + c] = h[i] * score[node];
}
__global__ void k_eflag(const int* src, const int* dst, const int* keep,
                        int* flag, const int* pE, int Emax){
    int e = blockIdx.x*blockDim.x + threadIdx.x;
    if (e >= Emax) return;
    int E = pE ? *pE : Emax;
    int f = 0;
    if (e < E) f = (keep[src[e]] && keep[dst[e]]) ? 1 : 0;
    flag[e] = f;
}
__global__ void k_ecompact(const int* src, const int* dst, const int* flag,
                           const int* pos, const int* nid, int* ns, int* nd, int Emax){
    int e = blockIdx.x*blockDim.x + threadIdx.x;
    if (e >= Emax) return;
    if (flag[e]) {
        int j = pos[e];
        ns[j] = nid[src[e]];
        nd[j] = nid[dst[e]];
    }
}

// ---------------------------------------------------------------------------
// GAT
// ---------------------------------------------------------------------------
__device__ __forceinline__ float lrelu(float x){ return x > 0.f ? x : 0.2f*x; }

__global__ void k_gat_coef(const float* __restrict__ xh, const float* __restrict__ as,
                           const float* __restrict__ adw, float* al, float* ad, int n){
    int i = blockIdx.x*blockDim.x + threadIdx.x;
    if (i >= n*HEADSc) return;
    int node = i / HEADSc, h = i % HEADSc;
    const float* r = xh + (size_t)node*(HEADSc*H2c) + h*H2c;
    float sl = 0, sd = 0;
    for (int c = 0; c < H2c; c++) { float v = r[c]; sl += v*as[h*H2c + c]; sd += v*adw[h*H2c + c]; }
    al[i] = sl; ad[i] = sd;
}
__global__ void k_gat_mxinit(float* mx, const float* al, const float* ad, int n){
    int i = blockIdx.x*blockDim.x + threadIdx.x;
    if (i >= n*HEADSc) return;
    mx[i] = lrelu(al[i] + ad[i]);     // self-loop value
}
__device__ void atomicMaxF(float* addr, float v){
    int* ia = (int*)addr;
    int old = *ia;
    while (__int_as_float(old) < v) {
        int assumed = old;
        old = atomicCAS(ia, assumed, __float_as_int(v));
        if (old == assumed) break;
    }
}
__global__ void k_gat_mxedge(const int* src, const int* dst, const float* al,
                             const float* ad, float* mx, const int* pE, int Emax){
    int e = blockIdx.x*blockDim.x + threadIdx.x;
    if (e >= Emax) return;
    if (e >= *pE) return;
    int s = src[e], d = dst[e];
    #pragma unroll
    for (int h = 0; h < HEADSc; h++)
        atomicMaxF(&mx[d*HEADSc + h], lrelu(al[s*HEADSc + h] + ad[d*HEADSc + h]));
}
__global__ void k_gat_dninit(float* dn, const float* al, const float* ad,
                             const float* mx, int n){
    int i = blockIdx.x*blockDim.x + threadIdx.x;
    if (i >= n*HEADSc) return;
    dn[i] = expf(lrelu(al[i] + ad[i]) - mx[i]);
}
__global__ void k_gat_dnedge(const int* src, const int* dst, const float* al,
                             const float* ad, const float* mx, float* dn,
                             const int* pE, int Emax){
    int e = blockIdx.x*blockDim.x + threadIdx.x;
    if (e >= Emax) return;
    if (e >= *pE) return;
    int s = src[e], d = dst[e];
    #pragma unroll
    for (int h = 0; h < HEADSc; h++) {
        int i = d*HEADSc + h;
        atomicAdd(&dn[i], expf(lrelu(al[s*HEADSc + h] + ad[i]) - mx[i]));
    }
}
__global__ void k_gat_aggself(const float* __restrict__ xh, const float* al,
                              const float* ad, const float* mx, const float* dn,
                              float* out, int n){
    int node = blockIdx.x;
    int c = threadIdx.x;                 // 128 threads
    __shared__ float att[HEADSc];
    if (c < HEADSc) {
        int i = node*HEADSc + c;
        att[c] = expf(lrelu(al[i] + ad[i]) - mx[i]) / dn[i] * 0.125f;
    }
    __syncthreads();
    float acc = 0;
    const float* r = xh + (size_t)node*(HEADSc*H2c);
    #pragma unroll
    for (int h = 0; h < HEADSc; h++) acc += att[h] * r[h*H2c + c];
    out[(size_t)node*H2c + c] = acc;
}
__global__ void k_gat_aggedge(const int* src, const int* dst,
                              const float* __restrict__ xh, const float* al,
                              const float* ad, const float* mx, const float* dn,
                              float* out, const int* pE, int Emax){
    int t = blockIdx.x*blockDim.x + threadIdx.x;
    int e = t >> 5, lane = t & 31;
    if (e >= Emax) return;
    if (e >= *pE) return;
    int s = src[e], d = dst[e];
    float att = 0.f;
    if (lane < HEADSc) {
        int i = d*HEADSc + lane;
        att = expf(lrelu(al[s*HEADSc + lane] + ad[i]) - mx[i]) / dn[i] * 0.125f;
    }
    float atts[HEADSc];
    #pragma unroll
    for (int h = 0; h < HEADSc; h++) atts[h] = __shfl_sync(0xFFFFFFFFu, att, h);
    const float* r = xh + (size_t)s*(HEADSc*H2c);
    float a0 = 0, a1 = 0, a2 = 0, a3 = 0;
    #pragma unroll
    for (int h = 0; h < HEADSc; h++) {
        const float* rh = r + h*H2c;
        a0 += atts[h]*rh[lane];
        a1 += atts[h]*rh[lane + 32];
        a2 += atts[h]*rh[lane + 64];
        a3 += atts[h]*rh[lane + 96];
    }
    float* o = out + (size_t)d*H2c;
    atomicAdd(&o[lane],      a0);
    atomicAdd(&o[lane + 32], a1);
    atomicAdd(&o[lane + 64], a2);
    atomicAdd(&o[lane + 96], a3);
}
__global__ void k_gat_finish(float* gat, const float* b, const float* xres,
                             float* gin, int n){
    int i = blockIdx.x*blockDim.x + threadIdx.x;
    if (i >= n*H2c) return;
    int c = i % H2c;
    float v = fmaxf(gat[i] + b[c], 0.f);
    gat[i] = v;
    gin[i] = v + xres[i];
}

// ---------------------------------------------------------------------------
// GCN
// ---------------------------------------------------------------------------
__global__ void k_deg_init(int* deg, int n){
    int i = blockIdx.x*blockDim.x + threadIdx.x;
    if (i < n) deg[i] = 1;               // self loop
}
__global__ void k_deg_edge(const int* dst, int* deg, const int* pE, int Emax){
    int e = blockIdx.x*blockDim.x + threadIdx.x;
    if (e >= Emax) return;
    if (e >= *pE) return;
    atomicAdd(&deg[dst[e]], 1);
}
__global__ void k_dinv(const int* deg, float* dinv, int n){
    int i = blockIdx.x*blockDim.x + threadIdx.x;
    if (i < n) dinv[i] = rsqrtf((float)deg[i]);
}
__global__ void k_gcn_self(const float* y, const float* dinv, float* o, int n, int C){
    int i = blockIdx.x*blockDim.x + threadIdx.x;
    if (i >= n*C) return;
    int node = i / C;
    float dv = dinv[node];
    o[i] = dv*dv*y[i];
}
__global__ void k_gcn_edge(const int* src, const int* dst, const float* __restrict__ y,
                           const float* dinv, float* o, int C, const int* pE, int Emax){
    int t = blockIdx.x*blockDim.x + threadIdx.x;
    int e = t >> 5, lane = t & 31;
    if (e >= Emax) return;
    if (e >= *pE) return;
    int s = src[e], d = dst[e];
    float coef = dinv[s]*dinv[d];
    for (int c = lane; c < C; c += 32)
        atomicAdd(&o[(size_t)d*C + c], coef * y[(size_t)s*C + c]);
}
__global__ void k_bias_act(float* o, const float* b, int n, int C, int relu){
    int i = blockIdx.x*blockDim.x + threadIdx.x;
    if (i >= n*C) return;
    int c = i % C;
    float v = o[i] + b[c];
    o[i] = relu ? fmaxf(v, 0.f) : v;
}

// ---------------------------------------------------------------------------
// Global mean pool + log_softmax
// ---------------------------------------------------------------------------
__global__ void k_colmean(const float* h, int rows, int C){
    int c = blockIdx.x;                  // C blocks
    float s = 0;
    for (int r = threadIdx.x; r < rows; r += 256) s += h[(size_t)r*C + c];
    __shared__ float sh[256];
    sh[threadIdx.x] = s; __syncthreads();
    for (int o = 128; o; o >>= 1) {
        if (threadIdx.x < o) sh[threadIdx.x] += sh[threadIdx.x + o];
        __syncthreads();
    }
    if (threadIdx.x == 0) d_gvec[c] = sh[0] / (float)rows;
}
__global__ void k_lsm(float* out, int C){
    if (threadIdx.x == 0) {
        float mxv = -1e30f;
        for (int c = 0; c < C; c++) mxv = fmaxf(mxv, d_gvec[c]);
        float s = 0;
        for (int c = 0; c < C; c++) s += expf(d_gvec[c] - mxv);
        float l = logf(s);
        for (int c = 0; c < C; c++) out[c] = d_gvec[c] - mxv - l;
    }
}

// ---------------------------------------------------------------------------
// Host side
// ---------------------------------------------------------------------------
static void gemm_launch(const float* A, const float* B, float* C, int M, int N, int K){
    dim3 grid(CDIV(N, BN), CDIV(M, BM));
    k_gemm<<<grid, 256>>>(A, B, C, M, N, K);
}

// exclusive scan of `in` (length n) into `out`; block sums via bs; total -> totalDev (optional)
static void scan_launch(const int* in, int* out, int* bs, int n, int* totalDev){
    int nb = CDIV(n, 512);
    k_scan1<<<nb, 512>>>(in, out, bs, n);
    k_scan2<<<1, 1024>>>(bs, nb, totalDev);
    k_scan3<<<nb, 512>>>(out, bs, n);
}

extern "C" void kernel_launch(void* const* d_in, const int* in_sizes, int n_in,
                              void* d_out, int out_size){
    const float* x    = (const float*)d_in[0];
    const int*   ei   = (const int*)  d_in[1];
    const float* s1wl = (const float*)d_in[3];
    const float* s1bl = (const float*)d_in[4];
    const float* s1wr = (const float*)d_in[5];
    const float* r1w  = (const float*)d_in[6];
    const float* r1b  = (const float*)d_in[7];
    const float* p1w  = (const float*)d_in[8];
    const float* s2wl = (const float*)d_in[9];
    const float* s2bl = (const float*)d_in[10];
    const float* s2wr = (const float*)d_in[11];
    const float* r2w  = (const float*)d_in[12];
    const float* r2b  = (const float*)d_in[13];
    const float* p2w  = (const float*)d_in[14];
    const float* gw   = (const float*)d_in[15];
    const float* gas  = (const float*)d_in[16];
    const float* gad  = (const float*)d_in[17];
    const float* gb   = (const float*)d_in[18];
    const float* g1w  = (const float*)d_in[19];
    const float* g1b  = (const float*)d_in[20];
    const float* g2w  = (const float*)d_in[21];
    const float* g2b  = (const float*)d_in[22];
    float* out = (float*)d_out;

    const int* src0 = ei;          // edge_index row 0
    const int* dst0 = ei + Ee;     // edge_index row 1

    // symbol addresses
    float *aggr, *gP, *gQ, *gR, *h1, *hp1, *h2, *hp2, *xh, *al, *ad, *mx, *dn;
    float *gat, *gin, *y1, *o1, *y2, *o2, *dinv, *score;
    int *cnt, *keep, *nid, *src1, *dst1, *src2, *dst2, *eflag, *escan, *ebs, *Ecnt, *deg;
    cudaGetSymbolAddress((void**)&aggr,  d_aggr);
    cudaGetSymbolAddress((void**)&cnt,   d_cnt);
    cudaGetSymbolAddress((void**)&gP,    d_gP);
    cudaGetSymbolAddress((void**)&gQ,    d_gQ);
    cudaGetSymbolAddress((void**)&gR,    d_gR);
    cudaGetSymbolAddress((void**)&h1,    d_h1);
    cudaGetSymbolAddress((void**)&hp1,   d_hp1);
    cudaGetSymbolAddress((void**)&h2,    d_h2);
    cudaGetSymbolAddress((void**)&hp2,   d_hp2);
    cudaGetSymbolAddress((void**)&xh,    d_xh);
    cudaGetSymbolAddress((void**)&al,    d_al);
    cudaGetSymbolAddress((void**)&ad,    d_ad);
    cudaGetSymbolAddress((void**)&mx,    d_mx);
    cudaGetSymbolAddress((void**)&dn,    d_dn);
    cudaGetSymbolAddress((void**)&gat,   d_gat);
    cudaGetSymbolAddress((void**)&gin,   d_gin);
    cudaGetSymbolAddress((void**)&y1,    d_y1);
    cudaGetSymbolAddress((void**)&o1,    d_o1);
    cudaGetSymbolAddress((void**)&y2,    d_y2);
    cudaGetSymbolAddress((void**)&o2,    d_o2);
    cudaGetSymbolAddress((void**)&deg,   d_deg);
    cudaGetSymbolAddress((void**)&dinv,  d_dinv);
    cudaGetSymbolAddress((void**)&score, d_score);
    cudaGetSymbolAddress((void**)&keep,  d_keep);
    cudaGetSymbolAddress((void**)&nid,   d_nid);
    cudaGetSymbolAddress((void**)&src1,  d_src1);
    cudaGetSymbolAddress((void**)&dst1,  d_dst1);
    cudaGetSymbolAddress((void**)&src2,  d_src2);
    cudaGetSymbolAddress((void**)&dst2,  d_dst2);
    cudaGetSymbolAddress((void**)&eflag, d_eflag);
    cudaGetSymbolAddress((void**)&escan, d_escan);
    cudaGetSymbolAddress((void**)&ebs,   d_ebs);
    cudaGetSymbolAddress((void**)&Ecnt,  d_Ecnt);

    const int EW_GRID = CDIV(Ee*32, 256);   // warp-per-edge grids
    const int ET_GRID = CDIV(Ee, 256);      // thread-per-edge grids

    // ============ Stage 1: SAGE1 on N nodes (128 -> 64) ============
    k_zero_f<<<CDIV(Nn*FIN, 256), 256>>>(aggr, Nn*FIN);
    k_zero_i<<<CDIV(Nn, 256), 256>>>(cnt, Nn);
    k_scatter<<<EW_GRID, 256>>>(src0, dst0, x, aggr, cnt, FIN, nullptr, Ee);
    k_meandiv<<<CDIV(Nn*FIN, 256), 256>>>(aggr, cnt, Nn, FIN);
    gemm_launch(aggr, s1wl, gP, Nn, H1c, FIN);
    gemm_launch(x,    s1wr, gQ, Nn, H1c, FIN);
    gemm_launch(x,    r1w,  gR, Nn, H1c, FIN);
    k_sage_combine<<<CDIV(Nn*H1c, 256), 256>>>(gP, gQ, gR, s1bl, r1b, h1, Nn, H1c);

    // ============ Pool 1 (N -> K1) ============
    k_wnorm<<<1, 128>>>(p1w, H1c);
    k_score<<<CDIV(Nn, 256), 256>>>(h1, p1w, score, Nn, H1c);
    k_rs_init<<<1, 32>>>(K1c);
    for (int p = 0; p < 4; p++) {
        k_rs_clear<<<1, 256>>>();
        k_rs_hist<<<CDIV(Nn, 256), 256>>>(score, Nn, p);
        k_rs_select<<<1, 1>>>(p);
    }
    k_tie_flag<<<CDIV(Nn, 256), 256>>>(score, eflag, Nn);
    scan_launch(eflag, escan, ebs, Nn, nullptr);
    k_keep<<<CDIV(Nn, 256), 256>>>(score, eflag, escan, keep, Nn);
    scan_launch(keep, nid, ebs, Nn, nullptr);
    k_pool_gather<<<CDIV(Nn*H1c, 256), 256>>>(h1, score, keep, nid, hp1, Nn, H1c);
    k_eflag<<<ET_GRID, 256>>>(src0, dst0, keep, eflag, nullptr, Ee);
    scan_launch(eflag, escan, ebs, Ee, Ecnt);                 // total -> Ecnt[0] = E1
    k_ecompact<<<ET_GRID, 256>>>(src0, dst0, eflag, escan, nid, src1, dst1, Ee);

    // ============ Stage 2: SAGE2 on K1 nodes (64 -> 128) ============
    k_zero_f<<<CDIV(K1c*H1c, 256), 256>>>(aggr, K1c*H1c);
    k_zero_i<<<CDIV(K1c, 256), 256>>>(cnt, K1c);
    k_scatter<<<EW_GRID, 256>>>(src1, dst1, hp1, aggr, cnt, H1c, Ecnt, Ee);
    k_meandiv<<<CDIV(K1c*H1c, 256), 256>>>(aggr, cnt, K1c, H1c);
    gemm_launch(aggr, s2wl, gP, K1c, H2c, H1c);
    gemm_launch(hp1,  s2wr, gQ, K1c, H2c, H1c);
    gemm_launch(hp1,  r2w,  gR, K1c, H2c, H1c);
    k_sage_combine<<<CDIV(K1c*H2c, 256), 256>>>(gP, gQ, gR, s2bl, r2b, h2, K1c, H2c);

    // ============ Pool 2 (K1 -> K2) ============
    k_wnorm<<<1, 128>>>(p2w, H2c);
    k_score<<<CDIV(K1c, 256), 256>>>(h2, p2w, score, K1c, H2c);
    k_rs_init<<<1, 32>>>(K2c);
    for (int p = 0; p < 4; p++) {
        k_rs_clear<<<1, 256>>>();
        k_rs_hist<<<CDIV(K1c, 256), 256>>>(score, K1c, p);
        k_rs_select<<<1, 1>>>(p);
    }
    k_tie_flag<<<CDIV(K1c, 256), 256>>>(score, eflag, K1c);
    scan_launch(eflag, escan, ebs, K1c, nullptr);
    k_keep<<<CDIV(K1c, 256), 256>>>(score, eflag, escan, keep, K1c);
    scan_launch(keep, nid, ebs, K1c, nullptr);
    k_pool_gather<<<CDIV(K1c*H2c, 256), 256>>>(h2, score, keep, nid, hp2, K1c, H2c);
    k_eflag<<<ET_GRID, 256>>>(src1, dst1, keep, eflag, Ecnt, Ee);
    scan_launch(eflag, escan, ebs, Ee, Ecnt + 1);             // total -> Ecnt[1] = E2
    k_ecompact<<<ET_GRID, 256>>>(src1, dst1, eflag, escan, nid, src2, dst2, Ee);

    // ============ GAT on K2 nodes ============
    gemm_launch(hp2, gw, xh, K2c, HEADSc*H2c, H2c);           // [12800, 1024]
    k_gat_coef<<<CDIV(K2c*HEADSc, 256), 256>>>(xh, gas, gad, al, ad, K2c);
    k_gat_mxinit<<<CDIV(K2c*HEADSc, 256), 256>>>(mx, al, ad, K2c);
    k_gat_mxedge<<<ET_GRID, 256>>>(src2, dst2, al, ad, mx, Ecnt + 1, Ee);
    k_gat_dninit<<<CDIV(K2c*HEADSc, 256), 256>>>(dn, al, ad, mx, K2c);
    k_gat_dnedge<<<ET_GRID, 256>>>(src2, dst2, al, ad, mx, dn, Ecnt + 1, Ee);
    k_gat_aggself<<<K2c, H2c>>>(xh, al, ad, mx, dn, gat, K2c);
    k_gat_aggedge<<<EW_GRID, 256>>>(src2, dst2, xh, al, ad, mx, dn, gat, Ecnt + 1, Ee);
    k_gat_finish<<<CDIV(K2c*H2c, 256), 256>>>(gat, gb, hp2, gin, K2c);

    // ============ GCN1 (128 -> 64, relu) ============
    k_deg_init<<<CDIV(K2c, 256), 256>>>(deg, K2c);
    k_deg_edge<<<ET_GRID, 256>>>(dst2, deg, Ecnt + 1, Ee);
    k_dinv<<<CDIV(K2c, 256), 256>>>(deg, dinv, K2c);
    gemm_launch(gin, g1w, y1, K2c, H1c, H2c);
    k_gcn_self<<<CDIV(K2c*H1c, 256), 256>>>(y1, dinv, o1, K2c, H1c);
    k_gcn_edge<<<EW_GRID, 256>>>(src2, dst2, y1, dinv, o1, H1c, Ecnt + 1, Ee);
    k_bias_act<<<CDIV(K2c*H1c, 256), 256>>>(o1, g1b, K2c, H1c, 1);

    // ============ GCN2 (64 -> 40) ============
    gemm_launch(o1, g2w, y2, K2c, NCc, H1c);
    k_gcn_self<<<CDIV(K2c*NCc, 256), 256>>>(y2, dinv, o2, K2c, NCc);
    k_gcn_edge<<<EW_GRID, 256>>>(src2, dst2, y2, dinv, o2, NCc, Ecnt + 1, Ee);
    k_bias_act<<<CDIV(K2c*NCc, 256), 256>>>(o2, g2b, K2c, NCc, 0);

    // ============ Global mean pool + log_softmax ============
    k_colmean<<<NCc, 256>>>(o2, K2c, NCc);
    k_lsm<<<1, 32>>>(out, NCc);
}

// round 3
// speedup vs baseline: 1.4775x; 1.4775x over previous
#include <cuda_runtime.h>
#include <math.h>
#include <stdint.h>

#define Nn    20000
#define Ee    320000
#define FIN   128
#define H1c   64
#define H2c   128
#define HEADSc 8
#define NCc   40
#define K1c   16000
#define K2c   12800

#define CDIV(a,b) (((a)+(b)-1)/(b))

// ---------------------------------------------------------------------------
// Device scratch (static, no runtime allocation)
// ---------------------------------------------------------------------------
__device__ float d_aggr[Nn*H1c];           // scatter accumulator (64 feats max)
__device__ int   d_cnt[Nn];
__device__ float d_gP[Nn*H2c];             // y buffer / SAGE2 P
__device__ float d_gQR[Nn*2*H2c];          // combined [wr | res] gemm output
__device__ float d_h1[Nn*H1c];
__device__ float d_hp1[K1c*H1c];
__device__ float d_h2[K1c*H2c];
__device__ float d_hp2[K2c*H2c];
__device__ float d_xh[K2c*HEADSc*H2c];     // 12800 x 1024
__device__ float d_va[FIN*16];             // 128 x 16 folded attention vecs
__device__ float d_alad[K2c*16];           // [n,16]: cols 0..7 = al, 8..15 = ad
__device__ float d_mx[K2c*HEADSc];
__device__ float d_dn[K2c*HEADSc];
__device__ float d_gat[K2c*H2c];
__device__ float d_gin[K2c*H2c];
__device__ float d_y1[K2c*H1c];
__device__ float d_o1[K2c*H1c];
__device__ float d_y2[K2c*NCc];
__device__ float d_o2[K2c*NCc];
__device__ int   d_deg[K2c];
__device__ float d_dinv[K2c];
__device__ float d_score[Nn];
__device__ int   d_keep[Nn];
__device__ int   d_nid[Nn];
__device__ int   d_src1[Ee], d_dst1[Ee], d_src2[Ee], d_dst2[Ee];
__device__ int   d_Ecnt[2];
__device__ float d_gvec[NCc];

// ---------------------------------------------------------------------------
// Utility
// ---------------------------------------------------------------------------
__global__ void k_zero_f(float* p, int n){
    int i = blockIdx.x*blockDim.x + threadIdx.x;
    if (i < n) p[i] = 0.f;
}
__global__ void k_zero_i(int* p, int n){
    int i = blockIdx.x*blockDim.x + threadIdx.x;
    if (i < n) p[i] = 0;
}

// ---------------------------------------------------------------------------
// Scatter-sum (warp per edge) + per-dst count
// ---------------------------------------------------------------------------
__global__ void k_scatter(const int* __restrict__ src, const int* __restrict__ dst,
                          const float* __restrict__ x, float* __restrict__ s,
                          int* __restrict__ cnt, int F, const int* pE, int Emax){
    int t = blockIdx.x*blockDim.x + threadIdx.x;
    int w = t >> 5, lane = t & 31;
    if (w >= Emax) return;
    int E = pE ? *pE : Emax;
    if (w >= E) return;
    int sn = src[w], dn = dst[w];
    const float* xr = x + (size_t)sn * F;
    float* sr = s + (size_t)dn * F;
    for (int c = lane; c < F; c += 32) atomicAdd(&sr[c], xr[c]);
    if (lane == 0) atomicAdd(&cnt[dn], 1);
}

// SAGE combine: h = relu(P(/cnt) + QR[:, :C] + bl) + QR[:, C:] + rb
__global__ void k_sage_combine(const float* __restrict__ P, const int* __restrict__ cnt,
                               const float* __restrict__ QR, const float* __restrict__ bl,
                               const float* __restrict__ rb, float* __restrict__ h,
                               int n, int C){
    int i = blockIdx.x*blockDim.x + threadIdx.x;
    if (i >= n*C) return;
    int node = i / C, c = i % C;
    float p = P[i];
    if (cnt) p /= fmaxf((float)cnt[node], 1.f);
    const float* qr = QR + (size_t)node*2*C;
    float v = p + qr[c] + bl[c];
    h[i] = fmaxf(v, 0.f) + qr[C + c] + rb[c];
}

// ---------------------------------------------------------------------------
// SGEMM: C[M,N] = A[M,K] @ B[K,N]  (row-major), 128x64 tile, 8x4 per thread.
// Optional: rowdiv (divide A rows by max(cnt,1)); B2 (dual weight: cols
// [0,Nh) from B, [Nh,2Nh) from B2; both K x Nh).
// K must be a multiple of 16 and of 4 (fp4-aligned rows).
// ---------------------------------------------------------------------------
#define GBM 128
#define GBN 64
#define GBK 16
__global__ void k_gemm(const float* __restrict__ A, const float* __restrict__ B,
                       const float* __restrict__ B2, const int* __restrict__ rowdiv,
                       float* __restrict__ C, int M, int N, int K, int Nh){
    __shared__ float As[GBK][GBM];
    __shared__ float Bs[GBK][GBN];
    int tid = threadIdx.x;                    // 256 threads
    int rowBase = blockIdx.y*GBM, colBase = blockIdx.x*GBN;
    const float* Bsel = B; int cb = colBase;
    int Nw = N;
    if (B2) {
        Nw = Nh;
        if (colBase >= Nh) { Bsel = B2; cb = colBase - Nh; }
    }
    int tr = tid >> 4, tc = tid & 15;
    float acc[8][4];
    #pragma unroll
    for (int i = 0; i < 8; i++)
        #pragma unroll
        for (int j = 0; j < 4; j++) acc[i][j] = 0.f;

    for (int k0 = 0; k0 < K; k0 += GBK) {
        #pragma unroll
        for (int l = 0; l < 2; l++) {
            int idx = tid + l*256;            // 0..511
            int r = idx >> 2, seg = idx & 3;
            int gr = rowBase + r;
            float4 v = make_float4(0.f,0.f,0.f,0.f);
            if (gr < M) {
                v = *reinterpret_cast<const float4*>(&A[(size_t)gr*K + k0 + seg*4]);
                if (rowdiv) {
                    float dv = 1.f/fmaxf((float)rowdiv[gr], 1.f);
                    v.x *= dv; v.y *= dv; v.z *= dv; v.w *= dv;
                }
            }
            As[seg*4+0][r] = v.x; As[seg*4+1][r] = v.y;
            As[seg*4+2][r] = v.z; As[seg*4+3][r] = v.w;
        }
        {
            int r = tid >> 4;                 // k row 0..15
            int c0 = (tid & 15) * 4;
            int gk = k0 + r;
            #pragma unroll
            for (int j = 0; j < 4; j++) {
                int gc = cb + c0 + j;
                Bs[r][c0+j] = (gc < Nw) ? Bsel[(size_t)gk*Nw + gc] : 0.f;
            }
        }
        __syncthreads();
        #pragma unroll
        for (int kk = 0; kk < GBK; kk++) {
            float a[8], b[4];
            #pragma unroll
            for (int i = 0; i < 8; i++) a[i] = As[kk][tr*8+i];
            #pragma unroll
            for (int j = 0; j < 4; j++) b[j] = Bs[kk][tc*4+j];
            #pragma unroll
            for (int i = 0; i < 8; i++)
                #pragma unroll
                for (int j = 0; j < 4; j++) acc[i][j] += a[i]*b[j];
        }
        __syncthreads();
    }
    #pragma unroll
    for (int i = 0; i < 8; i++) {
        int r = rowBase + tr*8+i;
        if (r >= M) continue;
        #pragma unroll
        for (int j = 0; j < 4; j++) {
            int c = colBase + tc*4+j;
            if (c < N) C[(size_t)r*N + c] = acc[i][j];
        }
    }
}

// ---------------------------------------------------------------------------
// TopK: score (warp per node, wnorm fused), then single-block exact
// radix-select + stable keep/nid compaction
// ---------------------------------------------------------------------------
__global__ void k_score(const float* __restrict__ h, const float* __restrict__ w,
                        float* score, int n, int F){
    __shared__ float red[256];
    __shared__ float s_wni;
    float s = 0;
    for (int i = threadIdx.x; i < F; i += 256) { float v = w[i]; s += v*v; }
    red[threadIdx.x] = s; __syncthreads();
    for (int o = 128; o; o >>= 1) {
        if (threadIdx.x < o) red[threadIdx.x] += red[threadIdx.x+o];
        __syncthreads();
    }
    if (threadIdx.x == 0) s_wni = rsqrtf(red[0]);
    __syncthreads();
    int wrp = threadIdx.x >> 5, lane = threadIdx.x & 31;
    int node = blockIdx.x*8 + wrp;
    if (node >= n) return;
    const float* r = h + (size_t)node*F;
    float d = 0;
    for (int c = lane; c < F; c += 32) d += r[c]*w[c];
    #pragma unroll
    for (int o = 16; o; o >>= 1) d += __shfl_down_sync(0xFFFFFFFFu, d, o);
    if (!lane) score[node] = tanhf(d * s_wni);
}

__device__ __forceinline__ unsigned fkey(float f){
    unsigned u = __float_as_uint(f);
    return (u & 0x80000000u) ? ~u : (u | 0x80000000u);
}

__device__ __forceinline__ int blk_scan_incl(int v, int tid, int* warpsum, int* total){
    __syncthreads();                           // protect warpsum reuse
    int lane = tid & 31, wid = tid >> 5;
    #pragma unroll
    for (int o = 1; o < 32; o <<= 1) {
        int t = __shfl_up_sync(0xFFFFFFFFu, v, o);
        if (lane >= o) v += t;
    }
    if (lane == 31) warpsum[wid] = v;
    __syncthreads();
    if (wid == 0) {
        int s = warpsum[lane];
        #pragma unroll
        for (int o = 1; o < 32; o <<= 1) {
            int t = __shfl_up_sync(0xFFFFFFFFu, s, o);
            if (lane >= o) s += t;
        }
        warpsum[lane] = s;
    }
    __syncthreads();
    *total = warpsum[31];
    return v + (wid ? warpsum[wid-1] : 0);
}

__global__ void k_select(const float* __restrict__ score, int n, int K,
                         int* __restrict__ keep, int* __restrict__ nid, int* ezero){
    __shared__ unsigned hist[256];
    __shared__ int warpsum[32];
    __shared__ unsigned sh_prefix; __shared__ int sh_krem;
    __shared__ int sh_tieOff, sh_keepOff;
    int tid = threadIdx.x;                     // 1024 threads
    if (tid == 0) { sh_prefix = 0u; sh_krem = K; if (ezero) *ezero = 0; }
    __syncthreads();
    for (int pass = 0; pass < 4; pass++) {
        if (tid < 256) hist[tid] = 0u;
        __syncthreads();
        int shift = 24 - 8*pass;
        unsigned pfx = sh_prefix;
        unsigned hm = (pass > 0) ? (0xFFFFFFFFu << (shift+8)) : 0u;
        for (int i = tid; i < n; i += 1024) {
            unsigned key = fkey(score[i]);
            if ((key & hm) == (pfx & hm))
                atomicAdd(&hist[(key >> shift) & 0xFFu], 1u);
        }
        __syncthreads();
        if (tid == 0) {
            unsigned k = (unsigned)sh_krem, cum = 0; int b = 0;
            for (int i = 255; i >= 0; i--) {
                unsigned c = hist[i];
                if (cum + c >= k) { b = i; break; }
                cum += c;
            }
            sh_prefix = pfx | ((unsigned)b << shift);
            sh_krem = (int)(k - cum);
        }
        __syncthreads();
    }
    unsigned prefix = sh_prefix; int krem = sh_krem;
    if (tid == 0) { sh_tieOff = 0; sh_keepOff = 0; }
    __syncthreads();
    for (int base = 0; base < n; base += 1024) {
        int i = base + tid;
        bool valid = i < n;
        unsigned key = valid ? fkey(score[i]) : 0u;
        int tie = (valid && key == prefix) ? 1 : 0;
        int tieTot;
        int tieIncl = blk_scan_incl(tie, tid, warpsum, &tieTot);
        int trank = sh_tieOff + tieIncl - tie;
        int kp = 0;
        if (valid) kp = (key > prefix) ? 1 : ((tie && trank < krem) ? 1 : 0);
        int kpTot;
        int kpIncl = blk_scan_incl(kp, tid, warpsum, &kpTot);
        if (valid) { keep[i] = kp; nid[i] = sh_keepOff + kpIncl - kp; }
        __syncthreads();
        if (tid == 0) { sh_tieOff += tieTot; sh_keepOff += kpTot; }
        __syncthreads();
    }
}

__global__ void k_pool_gather(const float* __restrict__ h, const float* __restrict__ score,
                              const int* __restrict__ keep, const int* __restrict__ nid,
                              float* __restrict__ out, int n, int F){
    int i = blockIdx.x*blockDim.x + threadIdx.x;
    if (i >= n*F) return;
    int node = i / F, c = i % F;
    if (keep[node]) out[(size_t)nid[node]*F + c] = h[i] * score[node];
}

// atomic-counter edge compaction (edge order irrelevant: commutative sums only)
__global__ void k_ecompact(const int* __restrict__ src, const int* __restrict__ dst,
                           const int* __restrict__ keep, const int* __restrict__ nid,
                           const int* pE, int Emax, int* __restrict__ ns,
                           int* __restrict__ nd, int* cntOut, int* deg){
    int e = blockIdx.x*blockDim.x + threadIdx.x;
    if (e >= Emax) return;
    int E = pE ? *pE : Emax;
    if (e >= E) return;
    int s = src[e], d = dst[e];
    if (keep[s] && keep[d]) {
        int j = atomicAdd(cntOut, 1);
        int nsd = nid[s], ndd = nid[d];
        ns[j] = nsd; nd[j] = ndd;
        if (deg) atomicAdd(&deg[ndd], 1);
    }
}

// ---------------------------------------------------------------------------
// GAT
// ---------------------------------------------------------------------------
__device__ __forceinline__ float lrelu(float x){ return x > 0.f ? x : 0.2f*x; }

// va[k][h]   = sum_c gw[k, h*128+c] * asrc[h,c]     (cols 0..7)
// va[k][8+h] = sum_c gw[k, h*128+c] * adst[h,c]     (cols 8..15)
__global__ void k_gat_va(const float* __restrict__ gw, const float* __restrict__ as,
                         const float* __restrict__ ad, float* __restrict__ va){
    int t = blockIdx.x*blockDim.x + threadIdx.x;
    int w = t >> 5, lane = t & 31;
    if (w >= FIN*16) return;
    int k = w >> 4, col = w & 15;
    int h = col & 7;
    const float* avec = ((col < 8) ? as : ad) + h*H2c;
    const float* grow = gw + (size_t)k*(HEADSc*H2c) + h*H2c;
    float s = 0;
    for (int c = lane; c < H2c; c += 32) s += grow[c]*avec[c];
    #pragma unroll
    for (int o = 16; o; o >>= 1) s += __shfl_down_sync(0xFFFFFFFFu, s, o);
    if (!lane) va[k*16 + col] = s;
}

__global__ void k_gat_mxinit(float* mx, const float* __restrict__ alad, int n){
    int i = blockIdx.x*blockDim.x + threadIdx.x;
    if (i >= n*HEADSc) return;
    int node = i / HEADSc, h = i % HEADSc;
    mx[i] = lrelu(alad[node*16 + h] + alad[node*16 + 8 + h]);
}
__device__ void atomicMaxF(float* addr, float v){
    int* ia = (int*)addr;
    int old = *ia;
    while (__int_as_float(old) < v) {
        int assumed = old;
        old = atomicCAS(ia, assumed, __float_as_int(v));
        if (old == assumed) break;
    }
}
__global__ void k_gat_mxedge(const int* __restrict__ src, const int* __restrict__ dst,
                             const float* __restrict__ alad, float* mx,
                             const int* pE, int Emax){
    int e = blockIdx.x*blockDim.x + threadIdx.x;
    if (e >= Emax) return;
    if (e >= *pE) return;
    int s = src[e], d = dst[e];
    #pragma unroll
    for (int h = 0; h < HEADSc; h++)
        atomicMaxF(&mx[d*HEADSc + h], lrelu(alad[s*16 + h] + alad[d*16 + 8 + h]));
}
__global__ void k_gat_dninit(float* dn, const float* __restrict__ alad,
                             const float* __restrict__ mx, int n){
    int i = blockIdx.x*blockDim.x + threadIdx.x;
    if (i >= n*HEADSc) return;
    int node = i / HEADSc, h = i % HEADSc;
    dn[i] = expf(lrelu(alad[node*16 + h] + alad[node*16 + 8 + h]) - mx[i]);
}
__global__ void k_gat_dnedge(const int* __restrict__ src, const int* __restrict__ dst,
                             const float* __restrict__ alad, const float* __restrict__ mx,
                             float* dn, const int* pE, int Emax){
    int e = blockIdx.x*blockDim.x + threadIdx.x;
    if (e >= Emax) return;
    if (e >= *pE) return;
    int s = src[e], d = dst[e];
    #pragma unroll
    for (int h = 0; h < HEADSc; h++) {
        int i = d*HEADSc + h;
        atomicAdd(&dn[i], expf(lrelu(alad[s*16 + h] + alad[d*16 + 8 + h]) - mx[i]));
    }
}
__global__ void k_gat_aggself(const float* __restrict__ xh, const float* __restrict__ alad,
                              const float* __restrict__ mx, const float* __restrict__ dn,
                              float* __restrict__ out, int n){
    int node = blockIdx.x;
    int c = threadIdx.x;                 // 128 threads
    __shared__ float att[HEADSc];
    if (c < HEADSc) {
        int i = node*HEADSc + c;
        att[c] = expf(lrelu(alad[node*16 + c] + alad[node*16 + 8 + c]) - mx[i]) / dn[i] * 0.125f;
    }
    __syncthreads();
    float acc = 0;
    const float* r = xh + (size_t)node*(HEADSc*H2c);
    #pragma unroll
    for (int h = 0; h < HEADSc; h++) acc += att[h] * r[h*H2c + c];
    out[(size_t)node*H2c + c] = acc;
}
__global__ void k_gat_aggedge(const int* __restrict__ src, const int* __restrict__ dst,
                              const float* __restrict__ xh, const float* __restrict__ alad,
                              const float* __restrict__ mx, const float* __restrict__ dn,
                              float* __restrict__ out, const int* pE, int Emax){
    int t = blockIdx.x*blockDim.x + threadIdx.x;
    int e = t >> 5, lane = t & 31;
    if (e >= Emax) return;
    if (e >= *pE) return;
    int s = src[e], d = dst[e];
    float att = 0.f;
    if (lane < HEADSc) {
        int i = d*HEADSc + lane;
        att = expf(lrelu(alad[s*16 + lane] + alad[d*16 + 8 + lane]) - mx[i]) / dn[i] * 0.125f;
    }
    float atts[HEADSc];
    #pragma unroll
    for (int h = 0; h < HEADSc; h++) atts[h] = __shfl_sync(0xFFFFFFFFu, att, h);
    const float* r = xh + (size_t)s*(HEADSc*H2c);
    float a0 = 0, a1 = 0, a2 = 0, a3 = 0;
    #pragma unroll
    for (int h = 0; h < HEADSc; h++) {
        const float* rh = r + h*H2c;
        a0 += atts[h]*rh[lane];
        a1 += atts[h]*rh[lane + 32];
        a2 += atts[h]*rh[lane + 64];
        a3 += atts[h]*rh[lane + 96];
    }
    float* o = out + (size_t)d*H2c;
    atomicAdd(&o[lane],      a0);
    atomicAdd(&o[lane + 32], a1);
    atomicAdd(&o[lane + 64], a2);
    atomicAdd(&o[lane + 96], a3);
}
__global__ void k_gat_finish(float* gat, const float* __restrict__ b,
                             const float* __restrict__ xres, float* gin, int n){
    int i = blockIdx.x*blockDim.x + threadIdx.x;
    if (i >= n*H2c) return;
    int c = i % H2c;
    float v = fmaxf(gat[i] + b[c], 0.f);
    gat[i] = v;
    gin[i] = v + xres[i];
}

// ---------------------------------------------------------------------------
// GCN
// ---------------------------------------------------------------------------
__global__ void k_deg_init(int* deg, int n){
    int i = blockIdx.x*blockDim.x + threadIdx.x;
    if (i < n) deg[i] = 1;               // self loop
}
__global__ void k_dinv(const int* __restrict__ deg, float* dinv, int n){
    int i = blockIdx.x*blockDim.x + threadIdx.x;
    if (i < n) dinv[i] = rsqrtf((float)deg[i]);
}
__global__ void k_gcn_self(const float* __restrict__ y, const float* __restrict__ dinv,
                           float* o, int n, int C){
    int i = blockIdx.x*blockDim.x + threadIdx.x;
    if (i >= n*C) return;
    int node = i / C;
    float dv = dinv[node];
    o[i] = dv*dv*y[i];
}
__global__ void k_gcn_edge(const int* __restrict__ src, const int* __restrict__ dst,
                           const float* __restrict__ y, const float* __restrict__ dinv,
                           float* o, int C, const int* pE, int Emax){
    int t = blockIdx.x*blockDim.x + threadIdx.x;
    int e = t >> 5, lane = t & 31;
    if (e >= Emax) return;
    if (e >= *pE) return;
    int s = src[e], d = dst[e];
    float coef = dinv[s]*dinv[d];
    for (int c = lane; c < C; c += 32)
        atomicAdd(&o[(size_t)d*C + c], coef * y[(size_t)s*C + c]);
}
__global__ void k_bias_act(float* o, const float* __restrict__ b, int n, int C, int relu){
    int i = blockIdx.x*blockDim.x + threadIdx.x;
    if (i >= n*C) return;
    int c = i % C;
    float v = o[i] + b[c];
    o[i] = relu ? fmaxf(v, 0.f) : v;
}

// ---------------------------------------------------------------------------
// Global mean pool + log_softmax
// ---------------------------------------------------------------------------
__global__ void k_colmean(const float* __restrict__ h, int rows, int C){
    int c = blockIdx.x;
    float s = 0;
    for (int r = threadIdx.x; r < rows; r += 256) s += h[(size_t)r*C + c];
    __shared__ float sh[256];
    sh[threadIdx.x] = s; __syncthreads();
    for (int o = 128; o; o >>= 1) {
        if (threadIdx.x < o) sh[threadIdx.x] += sh[threadIdx.x + o];
        __syncthreads();
    }
    if (threadIdx.x == 0) d_gvec[c] = sh[0] / (float)rows;
}
__global__ void k_lsm(float* out, int C){
    if (threadIdx.x == 0) {
        float mxv = -1e30f;
        for (int c = 0; c < C; c++) mxv = fmaxf(mxv, d_gvec[c]);
        float s = 0;
        for (int c = 0; c < C; c++) s += expf(d_gvec[c] - mxv);
        float l = logf(s);
        for (int c = 0; c < C; c++) out[c] = d_gvec[c] - mxv - l;
    }
}

// ---------------------------------------------------------------------------
// Host side
// ---------------------------------------------------------------------------
static void gemm_launch(const float* A, const float* B, const float* B2,
                        const int* rowdiv, float* C, int M, int N, int K, int Nh){
    dim3 grid(CDIV(N, GBN), CDIV(M, GBM));
    k_gemm<<<grid, 256>>>(A, B, B2, rowdiv, C, M, N, K, Nh);
}

extern "C" void kernel_launch(void* const* d_in, const int* in_sizes, int n_in,
                              void* d_out, int out_size){
    const float* x    = (const float*)d_in[0];
    const int*   ei   = (const int*)  d_in[1];
    const float* s1wl = (const float*)d_in[3];
    const float* s1bl = (const float*)d_in[4];
    const float* s1wr = (const float*)d_in[5];
    const float* r1w  = (const float*)d_in[6];
    const float* r1b  = (const float*)d_in[7];
    const float* p1w  = (const float*)d_in[8];
    const float* s2wl = (const float*)d_in[9];
    const float* s2bl = (const float*)d_in[10];
    const float* s2wr = (const float*)d_in[11];
    const float* r2w  = (const float*)d_in[12];
    const float* r2b  = (const float*)d_in[13];
    const float* p2w  = (const float*)d_in[14];
    const float* gw   = (const float*)d_in[15];
    const float* gas  = (const float*)d_in[16];
    const float* gad  = (const float*)d_in[17];
    const float* gb   = (const float*)d_in[18];
    const float* g1w  = (const float*)d_in[19];
    const float* g1b  = (const float*)d_in[20];
    const float* g2w  = (const float*)d_in[21];
    const float* g2b  = (const float*)d_in[22];
    float* out = (float*)d_out;

    const int* src0 = ei;
    const int* dst0 = ei + Ee;

    float *aggr, *gP, *gQR, *h1, *hp1, *h2, *hp2, *xh, *va, *alad, *mx, *dn;
    float *gat, *gin, *y1, *o1, *y2, *o2, *dinv, *score;
    int *cnt, *keep, *nid, *src1, *dst1, *src2, *dst2, *Ecnt, *deg;
    cudaGetSymbolAddress((void**)&aggr,  d_aggr);
    cudaGetSymbolAddress((void**)&cnt,   d_cnt);
    cudaGetSymbolAddress((void**)&gP,    d_gP);
    cudaGetSymbolAddress((void**)&gQR,   d_gQR);
    cudaGetSymbolAddress((void**)&h1,    d_h1);
    cudaGetSymbolAddress((void**)&hp1,   d_hp1);
    cudaGetSymbolAddress((void**)&h2,    d_h2);
    cudaGetSymbolAddress((void**)&hp2,   d_hp2);
    cudaGetSymbolAddress((void**)&xh,    d_xh);
    cudaGetSymbolAddress((void**)&va,    d_va);
    cudaGetSymbolAddress((void**)&alad,  d_alad);
    cudaGetSymbolAddress((void**)&mx,    d_mx);
    cudaGetSymbolAddress((void**)&dn,    d_dn);
    cudaGetSymbolAddress((void**)&gat,   d_gat);
    cudaGetSymbolAddress((void**)&gin,   d_gin);
    cudaGetSymbolAddress((void**)&y1,    d_y1);
    cudaGetSymbolAddress((void**)&o1,    d_o1);
    cudaGetSymbolAddress((void**)&y2,    d_y2);
    cudaGetSymbolAddress((void**)&o2,    d_o2);
    cudaGetSymbolAddress((void**)&deg,   d_deg);
    cudaGetSymbolAddress((void**)&dinv,  d_dinv);
    cudaGetSymbolAddress((void**)&score, d_score);
    cudaGetSymbolAddress((void**)&keep,  d_keep);
    cudaGetSymbolAddress((void**)&nid,   d_nid);
    cudaGetSymbolAddress((void**)&src1,  d_src1);
    cudaGetSymbolAddress((void**)&dst1,  d_dst1);
    cudaGetSymbolAddress((void**)&src2,  d_src2);
    cudaGetSymbolAddress((void**)&dst2,  d_dst2);
    cudaGetSymbolAddress((void**)&Ecnt,  d_Ecnt);

    const int EW_GRID = CDIV(Ee*32, 256);   // warp-per-edge grids
    const int ET_GRID = CDIV(Ee, 256);      // thread-per-edge grids

    // ============ SAGE1 (128 -> 64): gemm-first, scatter 64 feats ============
    gemm_launch(x, s1wl, nullptr, nullptr, gP, Nn, H1c, FIN, 0);       // y = x@wl
    k_zero_f<<<CDIV(Nn*H1c, 256), 256>>>(aggr, Nn*H1c);
    k_zero_i<<<CDIV(Nn, 256), 256>>>(cnt, Nn);
    k_scatter<<<EW_GRID, 256>>>(src0, dst0, gP, aggr, cnt, H1c, nullptr, Ee);
    gemm_launch(x, s1wr, r1w, nullptr, gQR, Nn, 2*H1c, FIN, H1c);      // [x@wr | x@res]
    k_sage_combine<<<CDIV(Nn*H1c, 256), 256>>>(aggr, cnt, gQR, s1bl, r1b, h1, Nn, H1c);

    // ============ Pool 1 (N -> K1) ============
    k_score<<<CDIV(Nn, 8), 256>>>(h1, p1w, score, Nn, H1c);
    k_select<<<1, 1024>>>(score, Nn, K1c, keep, nid, Ecnt);            // zeroes Ecnt[0]
    k_pool_gather<<<CDIV(Nn*H1c, 256), 256>>>(h1, score, keep, nid, hp1, Nn, H1c);
    k_ecompact<<<ET_GRID, 256>>>(src0, dst0, keep, nid, nullptr, Ee,
                                 src1, dst1, Ecnt, nullptr);

    // ============ SAGE2 (64 -> 128): scatter-first (64 feats) ============
    k_zero_f<<<CDIV(K1c*H1c, 256), 256>>>(aggr, K1c*H1c);
    k_zero_i<<<CDIV(K1c, 256), 256>>>(cnt, K1c);
    k_scatter<<<EW_GRID, 256>>>(src1, dst1, hp1, aggr, cnt, H1c, Ecnt, Ee);
    gemm_launch(aggr, s2wl, nullptr, cnt, gP, K1c, H2c, H1c, 0);       // mean@wl
    gemm_launch(hp1, s2wr, r2w, nullptr, gQR, K1c, 2*H2c, H1c, H2c);   // [h@wr | h@res]
    k_sage_combine<<<CDIV(K1c*H2c, 256), 256>>>(gP, nullptr, gQR, s2bl, r2b, h2, K1c, H2c);

    // ============ Pool 2 (K1 -> K2) + GCN degrees ============
    k_score<<<CDIV(K1c, 8), 256>>>(h2, p2w, score, K1c, H2c);
    k_select<<<1, 1024>>>(score, K1c, K2c, keep, nid, Ecnt + 1);       // zeroes Ecnt[1]
    k_pool_gather<<<CDIV(K1c*H2c, 256), 256>>>(h2, score, keep, nid, hp2, K1c, H2c);
    k_deg_init<<<CDIV(K2c, 256), 256>>>(deg, K2c);
    k_ecompact<<<ET_GRID, 256>>>(src1, dst1, keep, nid, Ecnt, Ee,
                                 src2, dst2, Ecnt + 1, deg);
    k_dinv<<<CDIV(K2c, 256), 256>>>(deg, dinv, K2c);

    // ============ GAT on K2 nodes ============
    k_gat_va<<<CDIV(FIN*16*32, 256), 256>>>(gw, gas, gad, va);
    gemm_launch(hp2, va, nullptr, nullptr, alad, K2c, 16, H2c, 0);     // [al | ad]
    gemm_launch(hp2, gw, nullptr, nullptr, xh, K2c, HEADSc*H2c, H2c, 0);
    k_gat_mxinit<<<CDIV(K2c*HEADSc, 256), 256>>>(mx, alad, K2c);
    k_gat_mxedge<<<ET_GRID, 256>>>(src2, dst2, alad, mx, Ecnt + 1, Ee);
    k_gat_dninit<<<CDIV(K2c*HEADSc, 256), 256>>>(dn, alad, mx, K2c);
    k_gat_dnedge<<<ET_GRID, 256>>>(src2, dst2, alad, mx, dn, Ecnt + 1, Ee);
    k_gat_aggself<<<K2c, H2c>>>(xh, alad, mx, dn, gat, K2c);
    k_gat_aggedge<<<EW_GRID, 256>>>(src2, dst2, xh, alad, mx, dn, gat, Ecnt + 1, Ee);
    k_gat_finish<<<CDIV(K2c*H2c, 256), 256>>>(gat, gb, hp2, gin, K2c);

    // ============ GCN1 (128 -> 64, relu) ============
    gemm_launch(gin, g1w, nullptr, nullptr, y1, K2c, H1c, H2c, 0);
    k_gcn_self<<<CDIV(K2c*H1c, 256), 256>>>(y1, dinv, o1, K2c, H1c);
    k_gcn_edge<<<EW_GRID, 256>>>(src2, dst2, y1, dinv, o1, H1c, Ecnt + 1, Ee);
    k_bias_act<<<CDIV(K2c*H1c, 256), 256>>>(o1, g1b, K2c, H1c, 1);

    // ============ GCN2 (64 -> 40) ============
    gemm_launch(o1, g2w, nullptr, nullptr, y2, K2c, NCc, H1c, 0);
    k_gcn_self<<<CDIV(K2c*NCc, 256), 256>>>(y2, dinv, o2, K2c, NCc);
    k_gcn_edge<<<EW_GRID, 256>>>(src2, dst2, y2, dinv, o2, NCc, Ecnt + 1, Ee);
    k_bias_act<<<CDIV(K2c*NCc, 256), 256>>>(o2, g2b, K2c, NCc, 0);

    // ============ Global mean pool + log_softmax ============
    k_colmean<<<NCc, 256>>>(o2, K2c, NCc);
    k_lsm<<<1, 32>>>(out, NCc);
}

// round 4
// speedup vs baseline: 1.7025x; 1.1522x over previous
#include <cuda_runtime.h>
#include <math.h>
#include <stdint.h>

#define Nn    20000
#define Ee    320000
#define FIN   128
#define H1c   64
#define H2c   128
#define HEADSc 8
#define NCc   40
#define K1c   16000
#define K2c   12800

#define CDIV(a,b) (((a)+(b)-1)/(b))

// ---------------------------------------------------------------------------
// Device scratch
// ---------------------------------------------------------------------------
__device__ float d_aggr[K1c*H1c];          // SAGE2 mean buffer
__device__ int   d_cnt[Nn];                // per-stage degree counts
__device__ int   d_rowptr[Nn+1];
__device__ int   d_wp[Nn];
__device__ int   d_csr[Ee];
__device__ float d_gP[Nn*H2c];
__device__ float d_gQR[Nn*2*H2c];
__device__ float d_h1[Nn*H1c];
__device__ float d_hp1[K1c*H1c];
__device__ float d_h2[K1c*H2c];
__device__ float d_hp2[K2c*H2c];
__device__ float d_xh[K2c*HEADSc*H2c];     // 12800 x 1024
__device__ float d_va[FIN*16];
__device__ float d_alad[K2c*16];           // cols 0..7 = al, 8..15 = ad
__device__ float d_att[Ee*HEADSc];         // normalized per-edge attention
__device__ float d_attself[K2c*HEADSc];
__device__ float d_gin[K2c*H2c];
__device__ float d_y1[K2c*H1c];
__device__ float d_o1[K2c*H1c];
__device__ float d_y2[K2c*NCc];
__device__ float d_o2[K2c*NCc];
__device__ float d_dinv[K2c];
__device__ float d_score[Nn];
__device__ int   d_keep[Nn];
__device__ int   d_nid[Nn];
__device__ int   d_src1[Ee], d_dst1[Ee], d_src2[Ee], d_dst2[Ee];
__device__ int   d_Ecnt[2];
__device__ float d_gvec[NCc];

// ---------------------------------------------------------------------------
// Utility
// ---------------------------------------------------------------------------
__global__ void k_zero_i(int* p, int n){
    int i = blockIdx.x*blockDim.x + threadIdx.x;
    if (i < n) p[i] = 0;
}

// ---------------------------------------------------------------------------
// CSR build: count, exclusive-scan (single block), fill
// ---------------------------------------------------------------------------
__global__ void k_count(const int* __restrict__ dst, int* __restrict__ cnt,
                        const int* pE, int Emax){
    int e = blockIdx.x*blockDim.x + threadIdx.x;
    if (e >= Emax) return;
    int E = pE ? *pE : Emax;
    if (e < E) atomicAdd(&cnt[dst[e]], 1);
}

__device__ __forceinline__ int blk_scan_incl(int v, int tid, int* warpsum, int* total){
    __syncthreads();
    int lane = tid & 31, wid = tid >> 5;
    #pragma unroll
    for (int o = 1; o < 32; o <<= 1) {
        int t = __shfl_up_sync(0xFFFFFFFFu, v, o);
        if (lane >= o) v += t;
    }
    if (lane == 31) warpsum[wid] = v;
    __syncthreads();
    if (wid == 0) {
        int s = warpsum[lane];
        #pragma unroll
        for (int o = 1; o < 32; o <<= 1) {
            int t = __shfl_up_sync(0xFFFFFFFFu, s, o);
            if (lane >= o) s += t;
        }
        warpsum[lane] = s;
    }
    __syncthreads();
    *total = warpsum[31];
    return v + (wid ? warpsum[wid-1] : 0);
}

__global__ void k_exscan(const int* __restrict__ deg, int* __restrict__ rowptr,
                         int* __restrict__ wp, int n){
    __shared__ int warpsum[32];
    __shared__ int sh_run;
    int tid = threadIdx.x;                  // 1024 threads
    if (tid == 0) sh_run = 0;
    __syncthreads();
    for (int base = 0; base < n; base += 1024) {
        int i = base + tid;
        int v = (i < n) ? deg[i] : 0;
        int tot;
        int incl = blk_scan_incl(v, tid, warpsum, &tot);
        int excl = sh_run + incl - v;
        if (i < n) { rowptr[i] = excl; wp[i] = excl; }
        __syncthreads();
        if (tid == 0) sh_run += tot;
        __syncthreads();
    }
    if (tid == 0) rowptr[n] = sh_run;
}

__global__ void k_fill(const int* __restrict__ src, const int* __restrict__ dst,
                       int* __restrict__ wp, int* __restrict__ csr,
                       const int* pE, int Emax){
    int e = blockIdx.x*blockDim.x + threadIdx.x;
    if (e >= Emax) return;
    int E = pE ? *pE : Emax;
    if (e >= E) return;
    int d = dst[e];
    int p = atomicAdd(&wp[d], 1);
    csr[p] = src[e];
}

// ---------------------------------------------------------------------------
// SAGE gathers (warp per node, 64 feats)
// ---------------------------------------------------------------------------
// SAGE1 fused: h = relu(mean_y + QR[:, :64] + bl) + QR[:, 64:] + rb
__global__ void k_sage1_gather(const int* __restrict__ rowptr, const int* __restrict__ csr,
                               const float* __restrict__ y, const float* __restrict__ QR,
                               const float* __restrict__ bl, const float* __restrict__ rb,
                               float* __restrict__ h, int n){
    int t = blockIdx.x*blockDim.x + threadIdx.x;
    int w = t >> 5, lane = t & 31;
    if (w >= n) return;
    int e0 = rowptr[w], e1 = rowptr[w+1];
    float a0 = 0.f, a1 = 0.f;
    for (int p = e0; p < e1; p++) {
        int s = csr[p];
        a0 += y[s*H1c + lane];
        a1 += y[s*H1c + 32 + lane];
    }
    float inv = 1.f / fmaxf((float)(e1 - e0), 1.f);
    a0 *= inv; a1 *= inv;
    const float* qr = QR + (size_t)w*2*H1c;
    h[w*H1c + lane]      = fmaxf(a0 + qr[lane]    + bl[lane],    0.f) + qr[H1c + lane]    + rb[lane];
    h[w*H1c + 32 + lane] = fmaxf(a1 + qr[32+lane] + bl[32+lane], 0.f) + qr[H1c + 32+lane] + rb[32+lane];
}

// plain mean gather (64 feats)
__global__ void k_mean_gather(const int* __restrict__ rowptr, const int* __restrict__ csr,
                              const float* __restrict__ x, float* __restrict__ out, int n){
    int t = blockIdx.x*blockDim.x + threadIdx.x;
    int w = t >> 5, lane = t & 31;
    if (w >= n) return;
    int e0 = rowptr[w], e1 = rowptr[w+1];
    float a0 = 0.f, a1 = 0.f;
    for (int p = e0; p < e1; p++) {
        int s = csr[p];
        a0 += x[s*H1c + lane];
        a1 += x[s*H1c + 32 + lane];
    }
    float inv = 1.f / fmaxf((float)(e1 - e0), 1.f);
    out[w*H1c + lane]      = a0 * inv;
    out[w*H1c + 32 + lane] = a1 * inv;
}

// SAGE2 combine: h = relu(P + QR[:, :C] + bl) + QR[:, C:] + rb  (P already mean)
__global__ void k_sage_combine(const float* __restrict__ P, const float* __restrict__ QR,
                               const float* __restrict__ bl, const float* __restrict__ rb,
                               float* __restrict__ h, int n, int C){
    int i = blockIdx.x*blockDim.x + threadIdx.x;
    if (i >= n*C) return;
    int node = i / C, c = i % C;
    const float* qr = QR + (size_t)node*2*C;
    float v = P[i] + qr[c] + bl[c];
    h[i] = fmaxf(v, 0.f) + qr[C + c] + rb[c];
}

// ---------------------------------------------------------------------------
// SGEMM: C[M,N] = A[M,K] @ B[K,N], 128x128 tile, BK=8, 8x8/thread (quadrants)
// Optional B2: cols [0,Nh) from B, [Nh,2Nh) from B2 (both K x Nh). K % 8 == 0.
// ---------------------------------------------------------------------------
#define GBM 128
#define GBN 128
#define GBK 8
__global__ void k_gemm(const float* __restrict__ A, const float* __restrict__ B,
                       const float* __restrict__ B2, float* __restrict__ C,
                       int M, int N, int K, int Nh){
    __shared__ float As[GBK][GBM];
    __shared__ float Bs[GBK][GBN];
    int tid = threadIdx.x;                    // 256 threads
    int rowBase = blockIdx.y*GBM, colBase = blockIdx.x*GBN;
    int tr = tid >> 4, tc = tid & 15;
    int ar = tid >> 1, aseg = (tid & 1) * 4;  // A: row, k-offset
    int br = tid >> 5, bc0 = (tid & 31) * 4;  // B: k-row, col base
    float acc[8][8];
    #pragma unroll
    for (int i = 0; i < 8; i++)
        #pragma unroll
        for (int j = 0; j < 8; j++) acc[i][j] = 0.f;

    for (int k0 = 0; k0 < K; k0 += GBK) {
        int gr = rowBase + ar;
        float4 av = make_float4(0.f,0.f,0.f,0.f);
        if (gr < M) av = *reinterpret_cast<const float4*>(&A[(size_t)gr*K + k0 + aseg]);
        As[aseg+0][ar] = av.x; As[aseg+1][ar] = av.y;
        As[aseg+2][ar] = av.z; As[aseg+3][ar] = av.w;
        int gk = k0 + br;
        #pragma unroll
        for (int j = 0; j < 4; j++) {
            int gc = colBase + bc0 + j;
            float v = 0.f;
            if (gc < N) {
                if (B2) v = (gc < Nh) ? B[(size_t)gk*Nh + gc] : B2[(size_t)gk*Nh + gc - Nh];
                else    v = B[(size_t)gk*N + gc];
            }
            Bs[br][bc0+j] = v;
        }
        __syncthreads();
        #pragma unroll
        for (int kk = 0; kk < GBK; kk++) {
            float a[8], b[8];
            #pragma unroll
            for (int i = 0; i < 4; i++) { a[i] = As[kk][tr*4+i]; a[4+i] = As[kk][64+tr*4+i]; }
            #pragma unroll
            for (int j = 0; j < 4; j++) { b[j] = Bs[kk][tc*4+j]; b[4+j] = Bs[kk][64+tc*4+j]; }
            #pragma unroll
            for (int i = 0; i < 8; i++)
                #pragma unroll
                for (int j = 0; j < 8; j++) acc[i][j] += a[i]*b[j];
        }
        __syncthreads();
    }
    #pragma unroll
    for (int i = 0; i < 8; i++) {
        int r = rowBase + ((i < 4) ? (tr*4 + i) : (64 + tr*4 + i - 4));
        if (r >= M) continue;
        #pragma unroll
        for (int j = 0; j < 8; j++) {
            int c = colBase + ((j < 4) ? (tc*4 + j) : (64 + tc*4 + j - 4));
            if (c < N) C[(size_t)r*N + c] = acc[i][j];
        }
    }
}

// ---------------------------------------------------------------------------
// TopK: score (warp per node, wnorm fused) + single-block radix select
// ---------------------------------------------------------------------------
__global__ void k_score(const float* __restrict__ h, const float* __restrict__ w,
                        float* score, int n, int F){
    __shared__ float red[256];
    __shared__ float s_wni;
    float s = 0;
    for (int i = threadIdx.x; i < F; i += 256) { float v = w[i]; s += v*v; }
    red[threadIdx.x] = s; __syncthreads();
    for (int o = 128; o; o >>= 1) {
        if (threadIdx.x < o) red[threadIdx.x] += red[threadIdx.x+o];
        __syncthreads();
    }
    if (threadIdx.x == 0) s_wni = rsqrtf(red[0]);
    __syncthreads();
    int wrp = threadIdx.x >> 5, lane = threadIdx.x & 31;
    int node = blockIdx.x*8 + wrp;
    if (node >= n) return;
    const float* r = h + (size_t)node*F;
    float d = 0;
    for (int c = lane; c < F; c += 32) d += r[c]*w[c];
    #pragma unroll
    for (int o = 16; o; o >>= 1) d += __shfl_down_sync(0xFFFFFFFFu, d, o);
    if (!lane) score[node] = tanhf(d * s_wni);
}

__device__ __forceinline__ unsigned fkey(float f){
    unsigned u = __float_as_uint(f);
    return (u & 0x80000000u) ? ~u : (u | 0x80000000u);
}

__global__ void k_select(const float* __restrict__ score, int n, int K,
                         int* __restrict__ keep, int* __restrict__ nid, int* ezero){
    __shared__ unsigned hist[256];
    __shared__ int warpsum[32];
    __shared__ unsigned sh_prefix; __shared__ int sh_krem;
    __shared__ int sh_tieOff, sh_keepOff;
    int tid = threadIdx.x;                     // 1024 threads
    if (tid == 0) { sh_prefix = 0u; sh_krem = K; if (ezero) *ezero = 0; }
    __syncthreads();
    for (int pass = 0; pass < 4; pass++) {
        if (tid < 256) hist[tid] = 0u;
        __syncthreads();
        int shift = 24 - 8*pass;
        unsigned pfx = sh_prefix;
        unsigned hm = (pass > 0) ? (0xFFFFFFFFu << (shift+8)) : 0u;
        for (int i = tid; i < n; i += 1024) {
            unsigned key = fkey(score[i]);
            if ((key & hm) == (pfx & hm))
                atomicAdd(&hist[(key >> shift) & 0xFFu], 1u);
        }
        __syncthreads();
        if (tid == 0) {
            unsigned k = (unsigned)sh_krem, cum = 0; int b = 0;
            for (int i = 255; i >= 0; i--) {
                unsigned c = hist[i];
                if (cum + c >= k) { b = i; break; }
                cum += c;
            }
            sh_prefix = pfx | ((unsigned)b << shift);
            sh_krem = (int)(k - cum);
        }
        __syncthreads();
    }
    unsigned prefix = sh_prefix; int krem = sh_krem;
    if (tid == 0) { sh_tieOff = 0; sh_keepOff = 0; }
    __syncthreads();
    for (int base = 0; base < n; base += 1024) {
        int i = base + tid;
        bool valid = i < n;
        unsigned key = valid ? fkey(score[i]) : 0u;
        int tie = (valid && key == prefix) ? 1 : 0;
        int tieTot;
        int tieIncl = blk_scan_incl(tie, tid, warpsum, &tieTot);
        int trank = sh_tieOff + tieIncl - tie;
        int kp = 0;
        if (valid) kp = (key > prefix) ? 1 : ((tie && trank < krem) ? 1 : 0);
        int kpTot;
        int kpIncl = blk_scan_incl(kp, tid, warpsum, &kpTot);
        if (valid) { keep[i] = kp; nid[i] = sh_keepOff + kpIncl - kp; }
        __syncthreads();
        if (tid == 0) { sh_tieOff += tieTot; sh_keepOff += kpTot; }
        __syncthreads();
    }
}

__global__ void k_pool_gather(const float* __restrict__ h, const float* __restrict__ score,
                              const int* __restrict__ keep, const int* __restrict__ nid,
                              float* __restrict__ out, int n, int F){
    int i = blockIdx.x*blockDim.x + threadIdx.x;
    if (i >= n*F) return;
    int node = i / F, c = i % F;
    if (keep[node]) out[(size_t)nid[node]*F + c] = h[i] * score[node];
}

// edge compaction (atomic order; sums downstream are commutative) + deg count
__global__ void k_ecompact(const int* __restrict__ src, const int* __restrict__ dst,
                           const int* __restrict__ keep, const int* __restrict__ nid,
                           const int* pE, int Emax, int* __restrict__ ns,
                           int* __restrict__ nd, int* cntOut, int* deg){
    int e = blockIdx.x*blockDim.x + threadIdx.x;
    if (e >= Emax) return;
    int E = pE ? *pE : Emax;
    if (e >= E) return;
    int s = src[e], d = dst[e];
    if (keep[s] && keep[d]) {
        int j = atomicAdd(cntOut, 1);
        int nsd = nid[s], ndd = nid[d];
        ns[j] = nsd; nd[j] = ndd;
        atomicAdd(&deg[ndd], 1);
    }
}

// ---------------------------------------------------------------------------
// GAT
// ---------------------------------------------------------------------------
__device__ __forceinline__ float lrelu(float x){ return x > 0.f ? x : 0.2f*x; }

// va[k][h] = sum_c gw[k, h*128+c]*asrc[h,c];  va[k][8+h] with adst
__global__ void k_gat_va(const float* __restrict__ gw, const float* __restrict__ as,
                         const float* __restrict__ ad, float* __restrict__ va){
    int t = blockIdx.x*blockDim.x + threadIdx.x;
    int w = t >> 5, lane = t & 31;
    if (w >= FIN*16) return;
    int k = w >> 4, col = w & 15;
    int h = col & 7;
    const float* avec = ((col < 8) ? as : ad) + h*H2c;
    const float* grow = gw + (size_t)k*(HEADSc*H2c) + h*H2c;
    float s = 0;
    for (int c = lane; c < H2c; c += 32) s += grow[c]*avec[c];
    #pragma unroll
    for (int o = 16; o; o >>= 1) s += __shfl_down_sync(0xFFFFFFFFu, s, o);
    if (!lane) va[k*16 + col] = s;
}

// thread per (node, head): softmax over in-edges + self loop, store normalized att
__global__ void k_gat_att(const int* __restrict__ rowptr, const int* __restrict__ csr,
                          const float* __restrict__ alad, float* __restrict__ att,
                          float* __restrict__ attself, int n){
    int t = blockIdx.x*blockDim.x + threadIdx.x;
    int node = t >> 3, h = t & 7;
    if (node >= n) return;
    int e0 = rowptr[node], e1 = rowptr[node+1];
    float add = alad[node*16 + 8 + h];
    float selfv = lrelu(alad[node*16 + h] + add);
    float m = selfv;
    for (int p = e0; p < e1; p++) {
        int s = csr[p];
        m = fmaxf(m, lrelu(alad[s*16 + h] + add));
    }
    float dn = expf(selfv - m);
    for (int p = e0; p < e1; p++) {
        int s = csr[p];
        float ex = expf(lrelu(alad[s*16 + h] + add) - m);
        att[p*8 + h] = ex;
        dn += ex;
    }
    float inv = 0.125f / dn;
    for (int p = e0; p < e1; p++) att[p*8 + h] *= inv;
    attself[node*8 + h] = expf(selfv - m) * inv;
}

// warp per node: gin = relu(sum_e,h att*xh[s,h,:] + b) + hp2
__global__ void k_gat_gather(const int* __restrict__ rowptr, const int* __restrict__ csr,
                             const float* __restrict__ xh, const float* __restrict__ att,
                             const float* __restrict__ attself, const float* __restrict__ gb,
                             const float* __restrict__ hp2, float* __restrict__ gin, int n){
    int t = blockIdx.x*blockDim.x + threadIdx.x;
    int w = t >> 5, lane = t & 31;
    if (w >= n) return;
    int e0 = rowptr[w], e1 = rowptr[w+1];
    float acc0 = 0.f, acc1 = 0.f, acc2 = 0.f, acc3 = 0.f;
    {   // self contribution
        float av = (lane < 8) ? attself[w*8 + lane] : 0.f;
        const float* xr = xh + (size_t)w*(HEADSc*H2c);
        #pragma unroll
        for (int h = 0; h < HEADSc; h++) {
            float a = __shfl_sync(0xFFFFFFFFu, av, h);
            const float* r = xr + h*H2c;
            acc0 += a*r[lane]; acc1 += a*r[lane+32];
            acc2 += a*r[lane+64]; acc3 += a*r[lane+96];
        }
    }
    for (int p = e0; p < e1; p++) {
        float av = (lane < 8) ? att[p*8 + lane] : 0.f;
        int s = csr[p];
        const float* r = xh + (size_t)s*(HEADSc*H2c);
        #pragma unroll
        for (int h = 0; h < HEADSc; h++) {
            float a = __shfl_sync(0xFFFFFFFFu, av, h);
            const float* rh = r + h*H2c;
            acc0 += a*rh[lane]; acc1 += a*rh[lane+32];
            acc2 += a*rh[lane+64]; acc3 += a*rh[lane+96];
        }
    }
    const float* hr = hp2 + (size_t)w*H2c;
    float* gr = gin + (size_t)w*H2c;
    gr[lane]    = fmaxf(acc0 + gb[lane],    0.f) + hr[lane];
    gr[lane+32] = fmaxf(acc1 + gb[lane+32], 0.f) + hr[lane+32];
    gr[lane+64] = fmaxf(acc2 + gb[lane+64], 0.f) + hr[lane+64];
    gr[lane+96] = fmaxf(acc3 + gb[lane+96], 0.f) + hr[lane+96];
}

// ---------------------------------------------------------------------------
// GCN: warp-per-node gather with fused self term + bias + activation
// ---------------------------------------------------------------------------
__global__ void k_dinv(const int* __restrict__ deg, float* dinv, int n){
    int i = blockIdx.x*blockDim.x + threadIdx.x;
    if (i < n) dinv[i] = rsqrtf((float)(deg[i] + 1));   // +1 self loop
}

__global__ void k_gcn_gather(const int* __restrict__ rowptr, const int* __restrict__ csr,
                             const float* __restrict__ y, const float* __restrict__ dinv,
                             const float* __restrict__ b, float* __restrict__ o,
                             int n, int C, int relu){
    int t = blockIdx.x*blockDim.x + threadIdx.x;
    int w = t >> 5, lane = t & 31;
    if (w >= n) return;
    int e0 = rowptr[w], e1 = rowptr[w+1];
    float dd = dinv[w];
    float a0 = 0.f, a1 = 0.f;
    bool has2 = (lane + 32) < C;
    for (int p = e0; p < e1; p++) {
        int s = csr[p];
        float ds = dinv[s];
        a0 += ds * y[(size_t)s*C + lane];
        if (has2) a1 += ds * y[(size_t)s*C + lane + 32];
    }
    float v0 = dd*a0 + dd*dd*y[(size_t)w*C + lane] + b[lane];
    o[(size_t)w*C + lane] = relu ? fmaxf(v0, 0.f) : v0;
    if (has2) {
        float v1 = dd*a1 + dd*dd*y[(size_t)w*C + lane + 32] + b[lane+32];
        o[(size_t)w*C + lane + 32] = relu ? fmaxf(v1, 0.f) : v1;
    }
}

// ---------------------------------------------------------------------------
// Global mean pool + log_softmax
// ---------------------------------------------------------------------------
__global__ void k_colmean(const float* __restrict__ h, int rows, int C){
    int c = blockIdx.x;
    float s = 0;
    for (int r = threadIdx.x; r < rows; r += 256) s += h[(size_t)r*C + c];
    __shared__ float sh[256];
    sh[threadIdx.x] = s; __syncthreads();
    for (int o = 128; o; o >>= 1) {
        if (threadIdx.x < o) sh[threadIdx.x] += sh[threadIdx.x + o];
        __syncthreads();
    }
    if (threadIdx.x == 0) d_gvec[c] = sh[0] / (float)rows;
}
__global__ void k_lsm(float* out, int C){
    if (threadIdx.x == 0) {
        float mxv = -1e30f;
        for (int c = 0; c < C; c++) mxv = fmaxf(mxv, d_gvec[c]);
        float s = 0;
        for (int c = 0; c < C; c++) s += expf(d_gvec[c] - mxv);
        float l = logf(s);
        for (int c = 0; c < C; c++) out[c] = d_gvec[c] - mxv - l;
    }
}

// ---------------------------------------------------------------------------
// Host side
// ---------------------------------------------------------------------------
static void gemm_launch(const float* A, const float* B, const float* B2,
                        float* C, int M, int N, int K, int Nh){
    dim3 grid(CDIV(N, GBN), CDIV(M, GBM));
    k_gemm<<<grid, 256>>>(A, B, B2, C, M, N, K, Nh);
}

extern "C" void kernel_launch(void* const* d_in, const int* in_sizes, int n_in,
                              void* d_out, int out_size){
    const float* x    = (const float*)d_in[0];
    const int*   ei   = (const int*)  d_in[1];
    const float* s1wl = (const float*)d_in[3];
    const float* s1bl = (const float*)d_in[4];
    const float* s1wr = (const float*)d_in[5];
    const float* r1w  = (const float*)d_in[6];
    const float* r1b  = (const float*)d_in[7];
    const float* p1w  = (const float*)d_in[8];
    const float* s2wl = (const float*)d_in[9];
    const float* s2bl = (const float*)d_in[10];
    const float* s2wr = (const float*)d_in[11];
    const float* r2w  = (const float*)d_in[12];
    const float* r2b  = (const float*)d_in[13];
    const float* p2w  = (const float*)d_in[14];
    const float* gw   = (const float*)d_in[15];
    const float* gas  = (const float*)d_in[16];
    const float* gad  = (const float*)d_in[17];
    const float* gb   = (const float*)d_in[18];
    const float* g1w  = (const float*)d_in[19];
    const float* g1b  = (const float*)d_in[20];
    const float* g2w  = (const float*)d_in[21];
    const float* g2b  = (const float*)d_in[22];
    float* out = (float*)d_out;

    const int* src0 = ei;
    const int* dst0 = ei + Ee;

    float *aggr, *gP, *gQR, *h1, *hp1, *h2, *hp2, *xh, *va, *alad, *att, *attself;
    float *gin, *y1, *o1, *y2, *o2, *dinv, *score;
    int *cnt, *rowptr, *wp, *csr, *keep, *nid, *src1, *dst1, *src2, *dst2, *Ecnt;
    cudaGetSymbolAddress((void**)&aggr,    d_aggr);
    cudaGetSymbolAddress((void**)&cnt,     d_cnt);
    cudaGetSymbolAddress((void**)&rowptr,  d_rowptr);
    cudaGetSymbolAddress((void**)&wp,      d_wp);
    cudaGetSymbolAddress((void**)&csr,     d_csr);
    cudaGetSymbolAddress((void**)&gP,      d_gP);
    cudaGetSymbolAddress((void**)&gQR,     d_gQR);
    cudaGetSymbolAddress((void**)&h1,      d_h1);
    cudaGetSymbolAddress((void**)&hp1,     d_hp1);
    cudaGetSymbolAddress((void**)&h2,      d_h2);
    cudaGetSymbolAddress((void**)&hp2,     d_hp2);
    cudaGetSymbolAddress((void**)&xh,      d_xh);
    cudaGetSymbolAddress((void**)&va,      d_va);
    cudaGetSymbolAddress((void**)&alad,    d_alad);
    cudaGetSymbolAddress((void**)&att,     d_att);
    cudaGetSymbolAddress((void**)&attself, d_attself);
    cudaGetSymbolAddress((void**)&gin,     d_gin);
    cudaGetSymbolAddress((void**)&y1,      d_y1);
    cudaGetSymbolAddress((void**)&o1,      d_o1);
    cudaGetSymbolAddress((void**)&y2,      d_y2);
    cudaGetSymbolAddress((void**)&o2,      d_o2);
    cudaGetSymbolAddress((void**)&dinv,    d_dinv);
    cudaGetSymbolAddress((void**)&score,   d_score);
    cudaGetSymbolAddress((void**)&keep,    d_keep);
    cudaGetSymbolAddress((void**)&nid,     d_nid);
    cudaGetSymbolAddress((void**)&src1,    d_src1);
    cudaGetSymbolAddress((void**)&dst1,    d_dst1);
    cudaGetSymbolAddress((void**)&src2,    d_src2);
    cudaGetSymbolAddress((void**)&dst2,    d_dst2);
    cudaGetSymbolAddress((void**)&Ecnt,    d_Ecnt);

    const int ET_GRID = CDIV(Ee, 256);

    // ============ SAGE1 (128 -> 64): GEMM-first + CSR gather ============
    gemm_launch(x, s1wl, nullptr, gP, Nn, H1c, FIN, 0);                // y = x@wl
    k_zero_i<<<CDIV(Nn, 256), 256>>>(cnt, Nn);
    k_count<<<ET_GRID, 256>>>(dst0, cnt, nullptr, Ee);
    k_exscan<<<1, 1024>>>(cnt, rowptr, wp, Nn);
    k_fill<<<ET_GRID, 256>>>(src0, dst0, wp, csr, nullptr, Ee);
    gemm_launch(x, s1wr, r1w, gQR, Nn, 2*H1c, FIN, H1c);               // [x@wr | x@res]
    k_sage1_gather<<<CDIV(Nn*32, 256), 256>>>(rowptr, csr, gP, gQR, s1bl, r1b, h1, Nn);

    // ============ Pool 1 (N -> K1) ============
    k_score<<<CDIV(Nn, 8), 256>>>(h1, p1w, score, Nn, H1c);
    k_select<<<1, 1024>>>(score, Nn, K1c, keep, nid, Ecnt);
    k_pool_gather<<<CDIV(Nn*H1c, 256), 256>>>(h1, score, keep, nid, hp1, Nn, H1c);
    k_zero_i<<<CDIV(K1c, 256), 256>>>(cnt, K1c);
    k_ecompact<<<ET_GRID, 256>>>(src0, dst0, keep, nid, nullptr, Ee,
                                 src1, dst1, Ecnt, cnt);
    k_exscan<<<1, 1024>>>(cnt, rowptr, wp, K1c);
    k_fill<<<ET_GRID, 256>>>(src1, dst1, wp, csr, Ecnt, Ee);

    // ============ SAGE2 (64 -> 128): gather-first ============
    k_mean_gather<<<CDIV(K1c*32, 256), 256>>>(rowptr, csr, hp1, aggr, K1c);
    gemm_launch(aggr, s2wl, nullptr, gP, K1c, H2c, H1c, 0);            // mean@wl
    gemm_launch(hp1, s2wr, r2w, gQR, K1c, 2*H2c, H1c, H2c);            // [h@wr | h@res]
    k_sage_combine<<<CDIV(K1c*H2c, 256), 256>>>(gP, gQR, s2bl, r2b, h2, K1c, H2c);

    // ============ Pool 2 (K1 -> K2) + graph2 CSR ============
    k_score<<<CDIV(K1c, 8), 256>>>(h2, p2w, score, K1c, H2c);
    k_select<<<1, 1024>>>(score, K1c, K2c, keep, nid, Ecnt + 1);
    k_pool_gather<<<CDIV(K1c*H2c, 256), 256>>>(h2, score, keep, nid, hp2, K1c, H2c);
    k_zero_i<<<CDIV(K2c, 256), 256>>>(cnt, K2c);
    k_ecompact<<<ET_GRID, 256>>>(src1, dst1, keep, nid, Ecnt, Ee,
                                 src2, dst2, Ecnt + 1, cnt);
    k_exscan<<<1, 1024>>>(cnt, rowptr, wp, K2c);
    k_fill<<<ET_GRID, 256>>>(src2, dst2, wp, csr, Ecnt + 1, Ee);
    k_dinv<<<CDIV(K2c, 256), 256>>>(cnt, dinv, K2c);

    // ============ GAT on K2 nodes ============
    k_gat_va<<<CDIV(FIN*16*32, 256), 256>>>(gw, gas, gad, va);
    gemm_launch(hp2, va, nullptr, alad, K2c, 16, H2c, 0);              // [al | ad]
    gemm_launch(hp2, gw, nullptr, xh, K2c, HEADSc*H2c, H2c, 0);
    k_gat_att<<<CDIV(K2c*8, 256), 256>>>(rowptr, csr, alad, att, attself, K2c);
    k_gat_gather<<<CDIV(K2c*32, 256), 256>>>(rowptr, csr, xh, att, attself, gb, hp2, gin, K2c);

    // ============ GCN1 (128 -> 64, relu) ============
    gemm_launch(gin, g1w, nullptr, y1, K2c, H1c, H2c, 0);
    k_gcn_gather<<<CDIV(K2c*32, 256), 256>>>(rowptr, csr, y1, dinv, g1b, o1, K2c, H1c, 1);

    // ============ GCN2 (64 -> 40) ============
    gemm_launch(o1, g2w, nullptr, y2, K2c, NCc, H1c, 0);
    k_gcn_gather<<<CDIV(K2c*32, 256), 256>>>(rowptr, csr, y2, dinv, g2b, o2, K2c, NCc, 0);

    // ============ Global mean pool + log_softmax ============
    k_colmean<<<NCc, 256>>>(o2, K2c, NCc);
    k_lsm<<<1, 32>>>(out, NCc);
}

// round 5
// speedup vs baseline: 1.8566x; 1.0905x over previous
#include <cuda_runtime.h>
#include <math.h>
#include <stdint.h>

#define Nn    20000
#define Ee    320000
#define FIN   128
#define H1c   64
#define H2c   128
#define HEADSc 8
#define NCc   40
#define K1c   16000
#define K2c   12800

#define CDIV(a,b) (((a)+(b)-1)/(b))

// ---------------------------------------------------------------------------
// Device scratch
// ---------------------------------------------------------------------------
__device__ float d_aggr[K1c*H1c];
__device__ int   d_cnt[Nn];
__device__ int   d_rowptr[Nn+1];
__device__ int   d_wp[Nn];
__device__ int   d_csr[Ee];
__device__ float d_gP[Nn*H2c];
__device__ float d_gQR[Nn*2*H2c];
__device__ float d_h1[Nn*H1c];
__device__ float d_hp1[K1c*H1c];
__device__ float d_h2[K1c*H2c];
__device__ float d_hp2[K2c*H2c];
__device__ float d_xh[K2c*HEADSc*H2c];     // 12800 x 1024
__device__ float d_va[FIN*16];
__device__ float d_alad[K2c*16];
__device__ float d_att[Ee*HEADSc];
__device__ float d_attself[K2c*HEADSc];
__device__ float d_gin[K2c*H2c];
__device__ float d_y1[K2c*H1c];
__device__ float d_o1[K2c*H1c];
__device__ float d_y2[K2c*NCc];
__device__ float d_o2[K2c*NCc];
__device__ float d_dinv[K2c];
__device__ float d_score[Nn];
__device__ int   d_keep[Nn];
__device__ int   d_nid[Nn];
__device__ int   d_src1[Ee], d_dst1[Ee], d_src2[Ee], d_dst2[Ee];
__device__ int   d_Ecnt[2];
__device__ float d_gvec[NCc];

// ---------------------------------------------------------------------------
// Utility
// ---------------------------------------------------------------------------
__global__ void k_zero_i(int* p, int n){
    int i = blockIdx.x*blockDim.x + threadIdx.x;
    if (i < n) p[i] = 0;
}

// ---------------------------------------------------------------------------
// CSR build
// ---------------------------------------------------------------------------
__global__ void k_count(const int* __restrict__ dst, int* __restrict__ cnt,
                        const int* pE, int Emax){
    int e = blockIdx.x*blockDim.x + threadIdx.x;
    if (e >= Emax) return;
    int E = pE ? *pE : Emax;
    if (e < E) atomicAdd(&cnt[dst[e]], 1);
}

__device__ __forceinline__ int blk_scan_incl(int v, int tid, int* warpsum, int* total){
    __syncthreads();
    int lane = tid & 31, wid = tid >> 5;
    #pragma unroll
    for (int o = 1; o < 32; o <<= 1) {
        int t = __shfl_up_sync(0xFFFFFFFFu, v, o);
        if (lane >= o) v += t;
    }
    if (lane == 31) warpsum[wid] = v;
    __syncthreads();
    if (wid == 0) {
        int s = warpsum[lane];
        #pragma unroll
        for (int o = 1; o < 32; o <<= 1) {
            int t = __shfl_up_sync(0xFFFFFFFFu, s, o);
            if (lane >= o) s += t;
        }
        warpsum[lane] = s;
    }
    __syncthreads();
    *total = warpsum[31];
    return v + (wid ? warpsum[wid-1] : 0);
}

// vectorized single-block exclusive scan: 4 ints per thread per iteration
// (n must be a multiple of 4; true for 20000/16000/12800)
__global__ void k_exscan(const int* __restrict__ deg, int* __restrict__ rowptr,
                         int* __restrict__ wp, int n){
    __shared__ int warpsum[32];
    __shared__ int sh_run;
    int tid = threadIdx.x;                  // 1024 threads
    if (tid == 0) sh_run = 0;
    __syncthreads();
    for (int base = 0; base < n; base += 4096) {
        int i0 = base + tid*4;
        int4 v = make_int4(0,0,0,0);
        if (i0 < n) v = *reinterpret_cast<const int4*>(deg + i0);
        int s = v.x + v.y + v.z + v.w;
        int tot;
        int incl = blk_scan_incl(s, tid, warpsum, &tot);
        int run = sh_run + incl - s;
        if (i0 < n) {
            rowptr[i0]   = run; wp[i0]   = run; run += v.x;
            rowptr[i0+1] = run; wp[i0+1] = run; run += v.y;
            rowptr[i0+2] = run; wp[i0+2] = run; run += v.z;
            rowptr[i0+3] = run; wp[i0+3] = run;
        }
        __syncthreads();
        if (tid == 0) sh_run += tot;
        __syncthreads();
    }
    if (tid == 0) rowptr[n] = sh_run;
}

__global__ void k_fill(const int* __restrict__ src, const int* __restrict__ dst,
                       int* __restrict__ wp, int* __restrict__ csr,
                       const int* pE, int Emax){
    int e = blockIdx.x*blockDim.x + threadIdx.x;
    if (e >= Emax) return;
    int E = pE ? *pE : Emax;
    if (e >= E) return;
    int d = dst[e];
    int p = atomicAdd(&wp[d], 1);
    csr[p] = src[e];
}

// ---------------------------------------------------------------------------
// SAGE gathers (warp per node, 64 feats)
// ---------------------------------------------------------------------------
__global__ void k_sage1_gather(const int* __restrict__ rowptr, const int* __restrict__ csr,
                               const float* __restrict__ y, const float* __restrict__ QR,
                               const float* __restrict__ bl, const float* __restrict__ rb,
                               float* __restrict__ h, int n){
    int t = blockIdx.x*blockDim.x + threadIdx.x;
    int w = t >> 5, lane = t & 31;
    if (w >= n) return;
    int e0 = rowptr[w], e1 = rowptr[w+1];
    float a0 = 0.f, a1 = 0.f;
    for (int p = e0; p < e1; p++) {
        int s = csr[p];
        a0 += y[s*H1c + lane];
        a1 += y[s*H1c + 32 + lane];
    }
    float inv = 1.f / fmaxf((float)(e1 - e0), 1.f);
    a0 *= inv; a1 *= inv;
    const float* qr = QR + (size_t)w*2*H1c;
    h[w*H1c + lane]      = fmaxf(a0 + qr[lane]    + bl[lane],    0.f) + qr[H1c + lane]    + rb[lane];
    h[w*H1c + 32 + lane] = fmaxf(a1 + qr[32+lane] + bl[32+lane], 0.f) + qr[H1c + 32+lane] + rb[32+lane];
}

__global__ void k_mean_gather(const int* __restrict__ rowptr, const int* __restrict__ csr,
                              const float* __restrict__ x, float* __restrict__ out, int n){
    int t = blockIdx.x*blockDim.x + threadIdx.x;
    int w = t >> 5, lane = t & 31;
    if (w >= n) return;
    int e0 = rowptr[w], e1 = rowptr[w+1];
    float a0 = 0.f, a1 = 0.f;
    for (int p = e0; p < e1; p++) {
        int s = csr[p];
        a0 += x[s*H1c + lane];
        a1 += x[s*H1c + 32 + lane];
    }
    float inv = 1.f / fmaxf((float)(e1 - e0), 1.f);
    out[w*H1c + lane]      = a0 * inv;
    out[w*H1c + 32 + lane] = a1 * inv;
}

__global__ void k_sage_combine(const float* __restrict__ P, const float* __restrict__ QR,
                               const float* __restrict__ bl, const float* __restrict__ rb,
                               float* __restrict__ h, int n, int C){
    int i = blockIdx.x*blockDim.x + threadIdx.x;
    if (i >= n*C) return;
    int node = i / C, c = i % C;
    const float* qr = QR + (size_t)node*2*C;
    float v = P[i] + qr[c] + bl[c];
    h[i] = fmaxf(v, 0.f) + qr[C + c] + rb[c];
}

// ---------------------------------------------------------------------------
// SGEMM: C = A@B, 128x128 tile, BK=16, double-buffered, 8x8/thread quadrants.
// Optional B2 (dual weight: cols [0,Nh) from B, [Nh,2Nh) from B2).
// Requires K % 16 == 0.
// ---------------------------------------------------------------------------
#define GBM 128
#define GBN 128
#define GBK 16
__global__ void __launch_bounds__(256)
k_gemm(const float* __restrict__ A, const float* __restrict__ B,
       const float* __restrict__ B2, float* __restrict__ C,
       int M, int N, int K, int Nh){
    __shared__ float As[2][GBK][GBM+4];
    __shared__ float Bs[2][GBK][GBN];
    int tid = threadIdx.x;                    // 256 threads
    int rowBase = blockIdx.y*GBM, colBase = blockIdx.x*GBN;
    int tr = tid >> 4, tc = tid & 15;
    int ar = tid >> 1, kseg = (tid & 1) * 8;  // A: row 0..127, k-offset 0/8
    int br = tid >> 4, bc0 = (tid & 15) * 8;  // B: k-row 0..15, col base
    float acc[8][8];
    #pragma unroll
    for (int i = 0; i < 8; i++)
        #pragma unroll
        for (int j = 0; j < 8; j++) acc[i][j] = 0.f;

    int nk = K / GBK;
    float4 pa0, pa1; float pb[8];
    // prefetch tile 0
    {
        int gr = rowBase + ar;
        pa0 = make_float4(0.f,0.f,0.f,0.f); pa1 = pa0;
        if (gr < M) {
            pa0 = *reinterpret_cast<const float4*>(&A[(size_t)gr*K + kseg]);
            pa1 = *reinterpret_cast<const float4*>(&A[(size_t)gr*K + kseg + 4]);
        }
        #pragma unroll
        for (int j = 0; j < 8; j++) {
            int gc = colBase + bc0 + j;
            float v = 0.f;
            if (gc < N) {
                if (B2) v = (gc < Nh) ? B[(size_t)br*Nh + gc] : B2[(size_t)br*Nh + gc - Nh];
                else    v = B[(size_t)br*N + gc];
            }
            pb[j] = v;
        }
    }
    As[0][kseg+0][ar]=pa0.x; As[0][kseg+1][ar]=pa0.y; As[0][kseg+2][ar]=pa0.z; As[0][kseg+3][ar]=pa0.w;
    As[0][kseg+4][ar]=pa1.x; As[0][kseg+5][ar]=pa1.y; As[0][kseg+6][ar]=pa1.z; As[0][kseg+7][ar]=pa1.w;
    #pragma unroll
    for (int j = 0; j < 8; j++) Bs[0][br][bc0+j] = pb[j];
    __syncthreads();

    for (int kt = 0; kt < nk; kt++) {
        int cur = kt & 1;
        if (kt + 1 < nk) {
            int k0 = (kt+1)*GBK;
            int gr = rowBase + ar;
            pa0 = make_float4(0.f,0.f,0.f,0.f); pa1 = pa0;
            if (gr < M) {
                pa0 = *reinterpret_cast<const float4*>(&A[(size_t)gr*K + k0 + kseg]);
                pa1 = *reinterpret_cast<const float4*>(&A[(size_t)gr*K + k0 + kseg + 4]);
            }
            int gk = k0 + br;
            #pragma unroll
            for (int j = 0; j < 8; j++) {
                int gc = colBase + bc0 + j;
                float v = 0.f;
                if (gc < N) {
                    if (B2) v = (gc < Nh) ? B[(size_t)gk*Nh + gc] : B2[(size_t)gk*Nh + gc - Nh];
                    else    v = B[(size_t)gk*N + gc];
                }
                pb[j] = v;
            }
        }
        #pragma unroll
        for (int kk = 0; kk < GBK; kk++) {
            float a[8], b[8];
            #pragma unroll
            for (int i = 0; i < 4; i++) { a[i] = As[cur][kk][tr*4+i]; a[4+i] = As[cur][kk][64+tr*4+i]; }
            #pragma unroll
            for (int j = 0; j < 4; j++) { b[j] = Bs[cur][kk][tc*4+j]; b[4+j] = Bs[cur][kk][64+tc*4+j]; }
            #pragma unroll
            for (int i = 0; i < 8; i++)
                #pragma unroll
                for (int j = 0; j < 8; j++) acc[i][j] += a[i]*b[j];
        }
        if (kt + 1 < nk) {
            int nb = 1 - cur;
            As[nb][kseg+0][ar]=pa0.x; As[nb][kseg+1][ar]=pa0.y; As[nb][kseg+2][ar]=pa0.z; As[nb][kseg+3][ar]=pa0.w;
            As[nb][kseg+4][ar]=pa1.x; As[nb][kseg+5][ar]=pa1.y; As[nb][kseg+6][ar]=pa1.z; As[nb][kseg+7][ar]=pa1.w;
            #pragma unroll
            for (int j = 0; j < 8; j++) Bs[nb][br][bc0+j] = pb[j];
        }
        __syncthreads();
    }
    #pragma unroll
    for (int i = 0; i < 8; i++) {
        int r = rowBase + ((i < 4) ? (tr*4 + i) : (64 + tr*4 + i - 4));
        if (r >= M) continue;
        #pragma unroll
        for (int j = 0; j < 8; j++) {
            int c = colBase + ((j < 4) ? (tc*4 + j) : (64 + tc*4 + j - 4));
            if (c < N) C[(size_t)r*N + c] = acc[i][j];
        }
    }
}

// ---------------------------------------------------------------------------
// TopK: score + single-block radix select (vectorized, packed single scan)
// ---------------------------------------------------------------------------
__global__ void k_score(const float* __restrict__ h, const float* __restrict__ w,
                        float* score, int n, int F){
    __shared__ float red[256];
    __shared__ float s_wni;
    float s = 0;
    for (int i = threadIdx.x; i < F; i += 256) { float v = w[i]; s += v*v; }
    red[threadIdx.x] = s; __syncthreads();
    for (int o = 128; o; o >>= 1) {
        if (threadIdx.x < o) red[threadIdx.x] += red[threadIdx.x+o];
        __syncthreads();
    }
    if (threadIdx.x == 0) s_wni = rsqrtf(red[0]);
    __syncthreads();
    int wrp = threadIdx.x >> 5, lane = threadIdx.x & 31;
    int node = blockIdx.x*8 + wrp;
    if (node >= n) return;
    const float* r = h + (size_t)node*F;
    float d = 0;
    for (int c = lane; c < F; c += 32) d += r[c]*w[c];
    #pragma unroll
    for (int o = 16; o; o >>= 1) d += __shfl_down_sync(0xFFFFFFFFu, d, o);
    if (!lane) score[node] = tanhf(d * s_wni);
}

__device__ __forceinline__ unsigned fkey(float f){
    unsigned u = __float_as_uint(f);
    return (u & 0x80000000u) ? ~u : (u | 0x80000000u);
}

// n must be a multiple of 4
__global__ void k_select(const float* __restrict__ score, int n, int K,
                         int* __restrict__ keep, int* __restrict__ nid, int* ezero){
    __shared__ unsigned hist[256];
    __shared__ int warpsum[32];
    __shared__ unsigned sh_prefix; __shared__ int sh_krem;
    __shared__ int sh_run;
    int tid = threadIdx.x;                     // 1024 threads
    if (tid == 0) { sh_prefix = 0u; sh_krem = K; if (ezero) *ezero = 0; }
    __syncthreads();
    for (int pass = 0; pass < 4; pass++) {
        if (tid < 256) hist[tid] = 0u;
        __syncthreads();
        int shift = 24 - 8*pass;
        unsigned pfx = sh_prefix;
        unsigned hm = (pass > 0) ? (0xFFFFFFFFu << (shift+8)) : 0u;
        for (int b = tid*4; b < n; b += 4096) {
            float4 v = *reinterpret_cast<const float4*>(score + b);
            unsigned k0 = fkey(v.x), k1 = fkey(v.y), k2 = fkey(v.z), k3 = fkey(v.w);
            if ((k0 & hm) == (pfx & hm)) atomicAdd(&hist[(k0 >> shift) & 0xFFu], 1u);
            if ((k1 & hm) == (pfx & hm)) atomicAdd(&hist[(k1 >> shift) & 0xFFu], 1u);
            if ((k2 & hm) == (pfx & hm)) atomicAdd(&hist[(k2 >> shift) & 0xFFu], 1u);
            if ((k3 & hm) == (pfx & hm)) atomicAdd(&hist[(k3 >> shift) & 0xFFu], 1u);
        }
        __syncthreads();
        if (tid == 0) {
            unsigned k = (unsigned)sh_krem, cum = 0; int b = 0;
            for (int i = 255; i >= 0; i--) {
                unsigned c = hist[i];
                if (cum + c >= k) { b = i; break; }
                cum += c;
            }
            sh_prefix = pfx | ((unsigned)b << shift);
            sh_krem = (int)(k - cum);
        }
        __syncthreads();
    }
    unsigned prefix = sh_prefix; int krem = sh_krem;
    if (tid == 0) sh_run = 0;
    __syncthreads();
    // single packed scan: p = (greater<<16) | tie ; fields never exceed n < 65536
    for (int base = 0; base < n; base += 4096) {
        int i0 = base + tid*4;
        int pk[4]; int s = 0;
        unsigned kk[4];
        if (i0 < n) {
            float4 v = *reinterpret_cast<const float4*>(score + i0);
            kk[0] = fkey(v.x); kk[1] = fkey(v.y); kk[2] = fkey(v.z); kk[3] = fkey(v.w);
            #pragma unroll
            for (int j = 0; j < 4; j++) {
                int g = (kk[j] > prefix) ? 1 : 0;
                int t = (kk[j] == prefix) ? 1 : 0;
                pk[j] = (g << 16) | t;
                s += pk[j];
            }
        } else { pk[0]=pk[1]=pk[2]=pk[3]=0; }
        int tot;
        int incl = blk_scan_incl(s, tid, warpsum, &tot);
        int run = sh_run + incl - s;
        if (i0 < n) {
            #pragma unroll
            for (int j = 0; j < 4; j++) {
                int g_before = run >> 16, t_before = run & 0xFFFF;
                int g = pk[j] >> 16, t = pk[j] & 0xFFFF;
                int kp = g | (t && (t_before < krem));
                keep[i0+j] = kp;
                nid[i0+j]  = g_before + (t_before < krem ? t_before : krem);
                run += pk[j];
            }
        }
        __syncthreads();
        if (tid == 0) sh_run += tot;
        __syncthreads();
    }
}

__global__ void k_pool_gather(const float* __restrict__ h, const float* __restrict__ score,
                              const int* __restrict__ keep, const int* __restrict__ nid,
                              float* __restrict__ out, int n, int F){
    int i = blockIdx.x*blockDim.x + threadIdx.x;
    if (i >= n*F) return;
    int node = i / F, c = i % F;
    if (keep[node]) out[(size_t)nid[node]*F + c] = h[i] * score[node];
}

__global__ void k_ecompact(const int* __restrict__ src, const int* __restrict__ dst,
                           const int* __restrict__ keep, const int* __restrict__ nid,
                           const int* pE, int Emax, int* __restrict__ ns,
                           int* __restrict__ nd, int* cntOut, int* deg){
    int e = blockIdx.x*blockDim.x + threadIdx.x;
    if (e >= Emax) return;
    int E = pE ? *pE : Emax;
    if (e >= E) return;
    int s = src[e], d = dst[e];
    if (keep[s] && keep[d]) {
        int j = atomicAdd(cntOut, 1);
        int nsd = nid[s], ndd = nid[d];
        ns[j] = nsd; nd[j] = ndd;
        atomicAdd(&deg[ndd], 1);
    }
}

// ---------------------------------------------------------------------------
// GAT
// ---------------------------------------------------------------------------
__device__ __forceinline__ float lrelu(float x){ return x > 0.f ? x : 0.2f*x; }

__global__ void k_gat_va(const float* __restrict__ gw, const float* __restrict__ as,
                         const float* __restrict__ ad, float* __restrict__ va){
    int t = blockIdx.x*blockDim.x + threadIdx.x;
    int w = t >> 5, lane = t & 31;
    if (w >= FIN*16) return;
    int k = w >> 4, col = w & 15;
    int h = col & 7;
    const float* avec = ((col < 8) ? as : ad) + h*H2c;
    const float* grow = gw + (size_t)k*(HEADSc*H2c) + h*H2c;
    float s = 0;
    for (int c = lane; c < H2c; c += 32) s += grow[c]*avec[c];
    #pragma unroll
    for (int o = 16; o; o >>= 1) s += __shfl_down_sync(0xFFFFFFFFu, s, o);
    if (!lane) va[k*16 + col] = s;
}

__global__ void k_gat_att(const int* __restrict__ rowptr, const int* __restrict__ csr,
                          const float* __restrict__ alad, float* __restrict__ att,
                          float* __restrict__ attself, int n){
    int t = blockIdx.x*blockDim.x + threadIdx.x;
    int node = t >> 3, h = t & 7;
    if (node >= n) return;
    int e0 = rowptr[node], e1 = rowptr[node+1];
    float add = alad[node*16 + 8 + h];
    float selfv = lrelu(alad[node*16 + h] + add);
    float m = selfv;
    for (int p = e0; p < e1; p++) {
        int s = csr[p];
        m = fmaxf(m, lrelu(alad[s*16 + h] + add));
    }
    float dn = expf(selfv - m);
    for (int p = e0; p < e1; p++) {
        int s = csr[p];
        float ex = expf(lrelu(alad[s*16 + h] + add) - m);
        att[p*8 + h] = ex;
        dn += ex;
    }
    float inv = 0.125f / dn;
    for (int p = e0; p < e1; p++) att[p*8 + h] *= inv;
    attself[node*8 + h] = expf(selfv - m) * inv;
}

__global__ void k_gat_gather(const int* __restrict__ rowptr, const int* __restrict__ csr,
                             const float* __restrict__ xh, const float* __restrict__ att,
                             const float* __restrict__ attself, const float* __restrict__ gb,
                             const float* __restrict__ hp2, float* __restrict__ gin, int n){
    int t = blockIdx.x*blockDim.x + threadIdx.x;
    int w = t >> 5, lane = t & 31;
    if (w >= n) return;
    int e0 = rowptr[w], e1 = rowptr[w+1];
    float acc0 = 0.f, acc1 = 0.f, acc2 = 0.f, acc3 = 0.f;
    {
        float av = (lane < 8) ? attself[w*8 + lane] : 0.f;
        const float* xr = xh + (size_t)w*(HEADSc*H2c);
        #pragma unroll
        for (int h = 0; h < HEADSc; h++) {
            float a = __shfl_sync(0xFFFFFFFFu, av, h);
            const float* r = xr + h*H2c;
            acc0 += a*r[lane]; acc1 += a*r[lane+32];
            acc2 += a*r[lane+64]; acc3 += a*r[lane+96];
        }
    }
    for (int p = e0; p < e1; p++) {
        float av = (lane < 8) ? att[p*8 + lane] : 0.f;
        int s = csr[p];
        const float* r = xh + (size_t)s*(HEADSc*H2c);
        #pragma unroll
        for (int h = 0; h < HEADSc; h++) {
            float a = __shfl_sync(0xFFFFFFFFu, av, h);
            const float* rh = r + h*H2c;
            acc0 += a*rh[lane]; acc1 += a*rh[lane+32];
            acc2 += a*rh[lane+64]; acc3 += a*rh[lane+96];
        }
    }
    const float* hr = hp2 + (size_t)w*H2c;
    float* gr = gin + (size_t)w*H2c;
    gr[lane]    = fmaxf(acc0 + gb[lane],    0.f) + hr[lane];
    gr[lane+32] = fmaxf(acc1 + gb[lane+32], 0.f) + hr[lane+32];
    gr[lane+64] = fmaxf(acc2 + gb[lane+64], 0.f) + hr[lane+64];
    gr[lane+96] = fmaxf(acc3 + gb[lane+96], 0.f) + hr[lane+96];
}

// ---------------------------------------------------------------------------
// GCN
// ---------------------------------------------------------------------------
__global__ void k_dinv(const int* __restrict__ deg, float* dinv, int n){
    int i = blockIdx.x*blockDim.x + threadIdx.x;
    if (i < n) dinv[i] = rsqrtf((float)(deg[i] + 1));
}

__global__ void k_gcn_gather(const int* __restrict__ rowptr, const int* __restrict__ csr,
                             const float* __restrict__ y, const float* __restrict__ dinv,
                             const float* __restrict__ b, float* __restrict__ o,
                             int n, int C, int relu){
    int t = blockIdx.x*blockDim.x + threadIdx.x;
    int w = t >> 5, lane = t & 31;
    if (w >= n) return;
    int e0 = rowptr[w], e1 = rowptr[w+1];
    float dd = dinv[w];
    float a0 = 0.f, a1 = 0.f;
    bool has2 = (lane + 32) < C;
    for (int p = e0; p < e1; p++) {
        int s = csr[p];
        float ds = dinv[s];
        a0 += ds * y[(size_t)s*C + lane];
        if (has2) a1 += ds * y[(size_t)s*C + lane + 32];
    }
    float v0 = dd*a0 + dd*dd*y[(size_t)w*C + lane] + b[lane];
    o[(size_t)w*C + lane] = relu ? fmaxf(v0, 0.f) : v0;
    if (has2) {
        float v1 = dd*a1 + dd*dd*y[(size_t)w*C + lane + 32] + b[lane+32];
        o[(size_t)w*C + lane + 32] = relu ? fmaxf(v1, 0.f) : v1;
    }
}

// ---------------------------------------------------------------------------
// Global mean pool + log_softmax
// ---------------------------------------------------------------------------
__global__ void k_colmean(const float* __restrict__ h, int rows, int C){
    int c = blockIdx.x;
    float s = 0;
    for (int r = threadIdx.x; r < rows; r += 256) s += h[(size_t)r*C + c];
    __shared__ float sh[256];
    sh[threadIdx.x] = s; __syncthreads();
    for (int o = 128; o; o >>= 1) {
        if (threadIdx.x < o) sh[threadIdx.x] += sh[threadIdx.x + o];
        __syncthreads();
    }
    if (threadIdx.x == 0) d_gvec[c] = sh[0] / (float)rows;
}
__global__ void k_lsm(float* out, int C){
    if (threadIdx.x == 0) {
        float mxv = -1e30f;
        for (int c = 0; c < C; c++) mxv = fmaxf(mxv, d_gvec[c]);
        float s = 0;
        for (int c = 0; c < C; c++) s += expf(d_gvec[c] - mxv);
        float l = logf(s);
        for (int c = 0; c < C; c++) out[c] = d_gvec[c] - mxv - l;
    }
}

// ---------------------------------------------------------------------------
// Host side
// ---------------------------------------------------------------------------
static void gemm_launch(const float* A, const float* B, const float* B2,
                        float* C, int M, int N, int K, int Nh){
    dim3 grid(CDIV(N, GBN), CDIV(M, GBM));
    k_gemm<<<grid, 256>>>(A, B, B2, C, M, N, K, Nh);
}

extern "C" void kernel_launch(void* const* d_in, const int* in_sizes, int n_in,
                              void* d_out, int out_size){
    const float* x    = (const float*)d_in[0];
    const int*   ei   = (const int*)  d_in[1];
    const float* s1wl = (const float*)d_in[3];
    const float* s1bl = (const float*)d_in[4];
    const float* s1wr = (const float*)d_in[5];
    const float* r1w  = (const float*)d_in[6];
    const float* r1b  = (const float*)d_in[7];
    const float* p1w  = (const float*)d_in[8];
    const float* s2wl = (const float*)d_in[9];
    const float* s2bl = (const float*)d_in[10];
    const float* s2wr = (const float*)d_in[11];
    const float* r2w  = (const float*)d_in[12];
    const float* r2b  = (const float*)d_in[13];
    const float* p2w  = (const float*)d_in[14];
    const float* gw   = (const float*)d_in[15];
    const float* gas  = (const float*)d_in[16];
    const float* gad  = (const float*)d_in[17];
    const float* gb   = (const float*)d_in[18];
    const float* g1w  = (const float*)d_in[19];
    const float* g1b  = (const float*)d_in[20];
    const float* g2w  = (const float*)d_in[21];
    const float* g2b  = (const float*)d_in[22];
    float* out = (float*)d_out;

    const int* src0 = ei;
    const int* dst0 = ei + Ee;

    float *aggr, *gP, *gQR, *h1, *hp1, *h2, *hp2, *xh, *va, *alad, *att, *attself;
    float *gin, *y1, *o1, *y2, *o2, *dinv, *score;
    int *cnt, *rowptr, *wp, *csr, *keep, *nid, *src1, *dst1, *src2, *dst2, *Ecnt;
    cudaGetSymbolAddress((void**)&aggr,    d_aggr);
    cudaGetSymbolAddress((void**)&cnt,     d_cnt);
    cudaGetSymbolAddress((void**)&rowptr,  d_rowptr);
    cudaGetSymbolAddress((void**)&wp,      d_wp);
    cudaGetSymbolAddress((void**)&csr,     d_csr);
    cudaGetSymbolAddress((void**)&gP,      d_gP);
    cudaGetSymbolAddress((void**)&gQR,     d_gQR);
    cudaGetSymbolAddress((void**)&h1,      d_h1);
    cudaGetSymbolAddress((void**)&hp1,     d_hp1);
    cudaGetSymbolAddress((void**)&h2,      d_h2);
    cudaGetSymbolAddress((void**)&hp2,     d_hp2);
    cudaGetSymbolAddress((void**)&xh,      d_xh);
    cudaGetSymbolAddress((void**)&va,      d_va);
    cudaGetSymbolAddress((void**)&alad,    d_alad);
    cudaGetSymbolAddress((void**)&att,     d_att);
    cudaGetSymbolAddress((void**)&attself, d_attself);
    cudaGetSymbolAddress((void**)&gin,     d_gin);
    cudaGetSymbolAddress((void**)&y1,      d_y1);
    cudaGetSymbolAddress((void**)&o1,      d_o1);
    cudaGetSymbolAddress((void**)&y2,      d_y2);
    cudaGetSymbolAddress((void**)&o2,      d_o2);
    cudaGetSymbolAddress((void**)&dinv,    d_dinv);
    cudaGetSymbolAddress((void**)&score,   d_score);
    cudaGetSymbolAddress((void**)&keep,    d_keep);
    cudaGetSymbolAddress((void**)&nid,     d_nid);
    cudaGetSymbolAddress((void**)&src1,    d_src1);
    cudaGetSymbolAddress((void**)&dst1,    d_dst1);
    cudaGetSymbolAddress((void**)&src2,    d_src2);
    cudaGetSymbolAddress((void**)&dst2,    d_dst2);
    cudaGetSymbolAddress((void**)&Ecnt,    d_Ecnt);

    const int ET_GRID = CDIV(Ee, 256);

    // ============ SAGE1 (128 -> 64): GEMM-first + CSR gather ============
    gemm_launch(x, s1wl, nullptr, gP, Nn, H1c, FIN, 0);
    k_zero_i<<<CDIV(Nn, 256), 256>>>(cnt, Nn);
    k_count<<<ET_GRID, 256>>>(dst0, cnt, nullptr, Ee);
    k_exscan<<<1, 1024>>>(cnt, rowptr, wp, Nn);
    k_fill<<<ET_GRID, 256>>>(src0, dst0, wp, csr, nullptr, Ee);
    gemm_launch(x, s1wr, r1w, gQR, Nn, 2*H1c, FIN, H1c);
    k_sage1_gather<<<CDIV(Nn*32, 256), 256>>>(rowptr, csr, gP, gQR, s1bl, r1b, h1, Nn);

    // ============ Pool 1 (N -> K1) ============
    k_score<<<CDIV(Nn, 8), 256>>>(h1, p1w, score, Nn, H1c);
    k_select<<<1, 1024>>>(score, Nn, K1c, keep, nid, Ecnt);
    k_pool_gather<<<CDIV(Nn*H1c, 256), 256>>>(h1, score, keep, nid, hp1, Nn, H1c);
    k_zero_i<<<CDIV(K1c, 256), 256>>>(cnt, K1c);
    k_ecompact<<<ET_GRID, 256>>>(src0, dst0, keep, nid, nullptr, Ee,
                                 src1, dst1, Ecnt, cnt);
    k_exscan<<<1, 1024>>>(cnt, rowptr, wp, K1c);
    k_fill<<<ET_GRID, 256>>>(src1, dst1, wp, csr, Ecnt, Ee);

    // ============ SAGE2 (64 -> 128): gather-first ============
    k_mean_gather<<<CDIV(K1c*32, 256), 256>>>(rowptr, csr, hp1, aggr, K1c);
    gemm_launch(aggr, s2wl, nullptr, gP, K1c, H2c, H1c, 0);
    gemm_launch(hp1, s2wr, r2w, gQR, K1c, 2*H2c, H1c, H2c);
    k_sage_combine<<<CDIV(K1c*H2c, 256), 256>>>(gP, gQR, s2bl, r2b, h2, K1c, H2c);

    // ============ Pool 2 (K1 -> K2) + graph2 CSR ============
    k_score<<<CDIV(K1c, 8), 256>>>(h2, p2w, score, K1c, H2c);
    k_select<<<1, 1024>>>(score, K1c, K2c, keep, nid, Ecnt + 1);
    k_pool_gather<<<CDIV(K1c*H2c, 256), 256>>>(h2, score, keep, nid, hp2, K1c, H2c);
    k_zero_i<<<CDIV(K2c, 256), 256>>>(cnt, K2c);
    k_ecompact<<<ET_GRID, 256>>>(src1, dst1, keep, nid, Ecnt, Ee,
                                 src2, dst2, Ecnt + 1, cnt);
    k_exscan<<<1, 1024>>>(cnt, rowptr, wp, K2c);
    k_fill<<<ET_GRID, 256>>>(src2, dst2, wp, csr, Ecnt + 1, Ee);
    k_dinv<<<CDIV(K2c, 256), 256>>>(cnt, dinv, K2c);

    // ============ GAT on K2 nodes ============
    k_gat_va<<<CDIV(FIN*16*32, 256), 256>>>(gw, gas, gad, va);
    gemm_launch(hp2, va, nullptr, alad, K2c, 16, H2c, 0);
    gemm_launch(hp2, gw, nullptr, xh, K2c, HEADSc*H2c, H2c, 0);
    k_gat_att<<<CDIV(K2c*8, 256), 256>>>(rowptr, csr, alad, att, attself, K2c);
    k_gat_gather<<<CDIV(K2c*32, 256), 256>>>(rowptr, csr, xh, att, attself, gb, hp2, gin, K2c);

    // ============ GCN1 (128 -> 64, relu) ============
    gemm_launch(gin, g1w, nullptr, y1, K2c, H1c, H2c, 0);
    k_gcn_gather<<<CDIV(K2c*32, 256), 256>>>(rowptr, csr, y1, dinv, g1b, o1, K2c, H1c, 1);

    // ============ GCN2 (64 -> 40) ============
    gemm_launch(o1, g2w, nullptr, y2, K2c, NCc, H1c, 0);
    k_gcn_gather<<<CDIV(K2c*32, 256), 256>>>(rowptr, csr, y2, dinv, g2b, o2, K2c, NCc, 0);

    // ============ Global mean pool + log_softmax ============
    k_colmean<<<NCc, 256>>>(o2, K2c, NCc);
    k_lsm<<<1, 32>>>(out, NCc);
}